// round 1
// baseline (speedup 1.0000x reference)
#include <cuda_runtime.h>
#include <math.h>

#define NV    4096
#define FIN   256
#define HH    128
#define MINC  1024
#define REPC  2
#define XR    6144   // NV + MINC*REPC

// ---------------- scratch (static __device__, no allocs) ----------------
__device__ __align__(16) float g_p0 [NV*FIN];
__device__ __align__(16) float g_hn0[NV*FIN];
__device__ __align__(16) float g_h  [NV*HH];
__device__ __align__(16) float g_p1 [NV*HH];
__device__ __align__(16) float g_hn1[NV*HH];
__device__ __align__(16) float g_x  [XR*HH];
__device__ __align__(16) float g_out[XR*HH];
__device__ __align__(16) float g_ng [XR*HH];
__device__ __align__(16) float g_sq [MINC];
__device__ __align__(16) float g_scal[4];     // 0: edge count, 1: neg_w, 2: loss
__device__ __align__(16) float g_weff[2*256];

// ---------------- init: zero segment-max buffers + scalars ----------------
__global__ void k_init() {
    int i = blockIdx.x*blockDim.x + threadIdx.x;
    int T = gridDim.x*blockDim.x;
    for (int t = i; t < NV*FIN; t += T) g_hn0[t] = 0.f;
    for (int t = i; t < NV*HH;  t += T) g_hn1[t] = 0.f;
    if (i == 0) { g_scal[0] = 0.f; g_scal[2] = 0.f; }
}

// ---------------- generic C = A @ B^T (+bias) (+=) (relu) ----------------
// A:[M,K] B:[N,K] row-major. Tile 32x32, BK=32. block (16,16), 2x2 per thread.
__global__ void k_sgemm(const float* __restrict__ A, const float* __restrict__ B,
                        const float* __restrict__ bias, float* __restrict__ C,
                        int M, int N, int K, int acc, int dorelu) {
    __shared__ float As[32][33];
    __shared__ float Bs[32][33];
    int tx = threadIdx.x, ty = threadIdx.y;
    int lin = ty*16 + tx;
    int m0 = blockIdx.y*32, n0 = blockIdx.x*32;
    float c00=0.f,c01=0.f,c10=0.f,c11=0.f;
    int lr = lin >> 3, lc = (lin & 7) << 2;
    for (int k0 = 0; k0 < K; k0 += 32) {
        float4 av = *(const float4*)&A[(size_t)(m0+lr)*K + k0 + lc];
        As[lr][lc]=av.x; As[lr][lc+1]=av.y; As[lr][lc+2]=av.z; As[lr][lc+3]=av.w;
        float4 bv = *(const float4*)&B[(size_t)(n0+lr)*K + k0 + lc];
        Bs[lr][lc]=bv.x; Bs[lr][lc+1]=bv.y; Bs[lr][lc+2]=bv.z; Bs[lr][lc+3]=bv.w;
        __syncthreads();
        #pragma unroll
        for (int kk = 0; kk < 32; kk++) {
            float a0 = As[ty*2][kk],   a1 = As[ty*2+1][kk];
            float b0 = Bs[tx*2][kk],   b1 = Bs[tx*2+1][kk];
            c00 += a0*b0; c01 += a0*b1; c10 += a1*b0; c11 += a1*b1;
        }
        __syncthreads();
    }
    int m = m0 + ty*2, n = n0 + tx*2;
    float bb0 = bias ? bias[n]   : 0.f;
    float bb1 = bias ? bias[n+1] : 0.f;
    float o00 = c00+bb0, o01 = c01+bb1, o10 = c10+bb0, o11 = c11+bb1;
    if (acc) {
        o00 += C[(size_t)m*N+n];     o01 += C[(size_t)m*N+n+1];
        o10 += C[(size_t)(m+1)*N+n]; o11 += C[(size_t)(m+1)*N+n+1];
    }
    if (dorelu) {
        o00 = fmaxf(o00,0.f); o01 = fmaxf(o01,0.f);
        o10 = fmaxf(o10,0.f); o11 = fmaxf(o11,0.f);
    }
    C[(size_t)m*N+n]     = o00; C[(size_t)m*N+n+1]     = o01;
    C[(size_t)(m+1)*N+n] = o10; C[(size_t)(m+1)*N+n+1] = o11;
}

// ---------------- segment max via atomicMax on int bits (values >= 0) ------
__global__ void k_scatter_max(const float* __restrict__ p, const int* __restrict__ src,
                              const int* __restrict__ dst, float* __restrict__ hn,
                              int E, int F) {
    int nc = F >> 2;
    int tid = blockIdx.x*blockDim.x + threadIdx.x;
    if (tid >= E*nc) return;
    int e = tid / nc, c = (tid - e*nc) << 2;
    int s = src[e], d = dst[e];
    float4 v = *(const float4*)&p[(size_t)s*F + c];
    int* o = (int*)&hn[(size_t)d*F + c];
    atomicMax(o+0, __float_as_int(v.x));
    atomicMax(o+1, __float_as_int(v.y));
    atomicMax(o+2, __float_as_int(v.z));
    atomicMax(o+3, __float_as_int(v.w));
}

// ---------------- relu + row l2norm (H=128), one block per row -------------
__global__ void k_relu_l2norm(float* __restrict__ h) {
    int r = blockIdx.x, t = threadIdx.x;
    float v = fmaxf(h[r*HH + t], 0.f);
    float s = v*v;
    #pragma unroll
    for (int o = 16; o; o >>= 1) s += __shfl_down_sync(0xffffffffu, s, o);
    __shared__ float ws[4];
    if ((t & 31) == 0) ws[t >> 5] = s;
    __syncthreads();
    float tot = ws[0] + ws[1] + ws[2] + ws[3];
    float nrm = fmaxf(sqrtf(tot), 1e-12f);
    h[r*HH + t] = v / nrm;
}

// ---------------- per-row squared norms of candidates ----------------------
__global__ void k_sq() {
    int r = blockIdx.x, t = threadIdx.x;
    float v = g_x[r*HH + t];
    float s = v*v;
    #pragma unroll
    for (int o = 16; o; o >>= 1) s += __shfl_down_sync(0xffffffffu, s, o);
    __shared__ float ws[4];
    if ((t & 31) == 0) ws[t >> 5] = s;
    __syncthreads();
    if (t == 0) g_sq[r] = ws[0] + ws[1] + ws[2] + ws[3];
}

// ---------------- SMOTE: NN (2nd smallest dist = argmin j!=i) + interp -----
__global__ void k_smote(const float* __restrict__ gaps) {
    int i = blockIdx.x, t = threadIdx.x;
    __shared__ float ci[HH];
    ci[t] = g_x[i*HH + t];
    __syncthreads();
    float sqi = g_sq[i];
    float best = 3.4e38f; int bestj = 0x7fffffff;
    for (int j = t; j < MINC; j += 128) {
        if (j == i) continue;
        const float* cj = &g_x[j*HH];
        float dot = 0.f;
        #pragma unroll 8
        for (int k = 0; k < HH; k++) dot += ci[k]*cj[k];
        float d2 = sqi + g_sq[j] - 2.f*dot;
        if (d2 < best || (d2 == best && j < bestj)) { best = d2; bestj = j; }
    }
    __shared__ float bd[128]; __shared__ int bj[128];
    bd[t] = best; bj[t] = bestj;
    __syncthreads();
    for (int s = 64; s; s >>= 1) {
        if (t < s) {
            if (bd[t+s] < bd[t] || (bd[t+s] == bd[t] && bj[t+s] < bj[t])) {
                bd[t] = bd[t+s]; bj[t] = bj[t+s];
            }
        }
        __syncthreads();
    }
    int nn = bj[0];
    float c = ci[t];
    float diff = g_x[nn*HH + t] - c;
    float g0 = gaps[i*REPC + 0], g1 = gaps[i*REPC + 1];
    g_x[(NV + 2*i    )*HH + t] = c + g0*diff;
    g_x[(NV + 2*i + 1)*HH + t] = c + g1*diff;
}

// ---------------- count nonzero adj entries --------------------------------
__global__ void k_count(const float* __restrict__ adj) {
    int i = blockIdx.x*blockDim.x + threadIdx.x;
    int T = gridDim.x*blockDim.x;
    float c = 0.f;
    for (long t = i; t < (long)NV*NV; t += T) c += (adj[t] != 0.f) ? 1.f : 0.f;
    #pragma unroll
    for (int o = 16; o; o >>= 1) c += __shfl_down_sync(0xffffffffu, c, o);
    __shared__ float ws[8];
    int tt = threadIdx.x;
    if ((tt & 31) == 0) ws[tt >> 5] = c;
    __syncthreads();
    if (tt == 0) {
        float s = 0.f;
        for (int q = 0; q < (int)(blockDim.x >> 5); q++) s += ws[q];
        atomicAdd(&g_scal[0], s);
    }
}
__global__ void k_negw() {
    float e = g_scal[0];
    g_scal[1] = e / (16777216.f - e);
}

// ---------------- fused: gram -> sigmoid -> loss -> threshold -> neigh -----
// Block handles 32 i-rows; sweeps all 192 j-tiles of 32.
__global__ void __launch_bounds__(256) k_fused(const float* __restrict__ adj) {
    __shared__ __align__(16) float soi[32*HH];
    __shared__ __align__(16) float soj[32*HH];
    __shared__ __align__(16) float sxj[32*HH];
    __shared__ float Pt[32][33];
    __shared__ float lred[8];

    int t  = threadIdx.x;
    int i0 = blockIdx.x * 32;

    // load out_i tile once
    for (int l = t; l < 32*HH/4; l += 256)
        *(float4*)&soi[l*4] = *(const float4*)&g_out[(size_t)i0*HH + l*4];

    // P mapping
    int cP = t & 31;        // gram column within tile
    int rg = t >> 5;        // row group (4 rows)
    // neigh mapping
    int r2 = t >> 3;        // neigh row 0..31
    int h0 = (t & 7) * 16;  // 16 feature columns

    float acc[16];
    #pragma unroll
    for (int q = 0; q < 16; q++) acc[q] = 0.f;
    float rsum  = 0.f;
    float lloss = 0.f;
    float negw  = g_scal[1];

    for (int j0 = 0; j0 < XR; j0 += 32) {
        __syncthreads();
        for (int l = t; l < 32*HH/4; l += 256) {
            *(float4*)&soj[l*4] = *(const float4*)&g_out[(size_t)j0*HH + l*4];
            *(float4*)&sxj[l*4] = *(const float4*)&g_x  [(size_t)j0*HH + l*4];
        }
        __syncthreads();

        // gram dots: thread computes P[rg*4+rr][cP]
        float dp0=0.f, dp1=0.f, dp2=0.f, dp3=0.f;
        #pragma unroll 8
        for (int k4 = 0; k4 < 32; k4++) {
            float4 b = *(float4*)&soj[cP*HH + k4*4];
            float4 a0 = *(float4*)&soi[(rg*4+0)*HH + k4*4];
            float4 a1 = *(float4*)&soi[(rg*4+1)*HH + k4*4];
            float4 a2 = *(float4*)&soi[(rg*4+2)*HH + k4*4];
            float4 a3 = *(float4*)&soi[(rg*4+3)*HH + k4*4];
            dp0 += a0.x*b.x + a0.y*b.y + a0.z*b.z + a0.w*b.w;
            dp1 += a1.x*b.x + a1.y*b.y + a1.z*b.z + a1.w*b.w;
            dp2 += a2.x*b.x + a2.y*b.y + a2.z*b.z + a2.w*b.w;
            dp3 += a3.x*b.x + a3.y*b.y + a3.z*b.z + a3.w*b.w;
        }
        float dps[4] = {dp0, dp1, dp2, dp3};
        bool jin = (j0 < NV);
        #pragma unroll
        for (int rr = 0; rr < 4; rr++) {
            int gi = i0 + rg*4 + rr;
            float pv = 1.f / (1.f + __expf(-dps[rr]));
            if (jin && gi < NV) {
                float a = adj[(size_t)gi*NV + j0 + cP];
                float w = (a == 0.f) ? negw : 1.f;
                float df = pv - a;
                lloss += w*df*df;
            }
            Pt[rg*4+rr][cP] = (pv >= 0.5f) ? pv : 0.f;
        }
        __syncthreads();

        // neigh accumulation: acc[r2][h0..h0+15] += Pt[r2][tj]*x_j[tj][h]
        #pragma unroll 4
        for (int tj = 0; tj < 32; tj++) {
            float p = Pt[r2][tj];
            rsum += p;
            const float4* xr = (const float4*)&sxj[tj*HH + h0];
            float4 x0 = xr[0], x1 = xr[1], x2 = xr[2], x3 = xr[3];
            acc[0]  += p*x0.x; acc[1]  += p*x0.y; acc[2]  += p*x0.z; acc[3]  += p*x0.w;
            acc[4]  += p*x1.x; acc[5]  += p*x1.y; acc[6]  += p*x1.z; acc[7]  += p*x1.w;
            acc[8]  += p*x2.x; acc[9]  += p*x2.y; acc[10] += p*x2.z; acc[11] += p*x2.w;
            acc[12] += p*x3.x; acc[13] += p*x3.y; acc[14] += p*x3.z; acc[15] += p*x3.w;
        }
    }
    // rsum is already the full row sum (every h-group thread of r2 reads all columns)
    float inv = 1.f / (rsum + 1.f);
    int gi = i0 + r2;
    #pragma unroll
    for (int q = 0; q < 16; q++) g_ng[(size_t)gi*HH + h0 + q] = acc[q]*inv;

    // loss reduction
    #pragma unroll
    for (int o = 16; o; o >>= 1) lloss += __shfl_down_sync(0xffffffffu, lloss, o);
    if ((t & 31) == 0) lred[t >> 5] = lloss;
    __syncthreads();
    if (t == 0) {
        float s = 0.f;
        for (int q = 0; q < 8; q++) s += lred[q];
        atomicAdd(&g_scal[2], s);
    }
}

// ---------------- W_eff = W_clf @ W_conv  [2,256] --------------------------
__global__ void k_weff(const float* __restrict__ Wclf, const float* __restrict__ Wconv) {
    int t = blockIdx.x*blockDim.x + threadIdx.x;
    if (t >= 512) return;
    int c = t >> 8, k = t & 255;
    float s = 0.f;
    for (int o = 0; o < HH; o++) s += Wclf[c*HH + o] * Wconv[o*256 + k];
    g_weff[c*256 + k] = s;
}

// ---------------- logits: warp per row -------------------------------------
__global__ void k_final(const float* __restrict__ bclf, float* __restrict__ ob) {
    int w = (blockIdx.x*blockDim.x + threadIdx.x) >> 5;
    int lane = threadIdx.x & 31;
    if (w >= XR) return;
    float l0 = 0.f, l1 = 0.f;
    for (int k = lane; k < HH; k += 32) {
        float xv = g_x[(size_t)w*HH + k];
        float nv = g_ng[(size_t)w*HH + k];
        l0 += xv*g_weff[k]       + nv*g_weff[128 + k];
        l1 += xv*g_weff[256 + k] + nv*g_weff[256 + 128 + k];
    }
    #pragma unroll
    for (int o = 16; o; o >>= 1) {
        l0 += __shfl_down_sync(0xffffffffu, l0, o);
        l1 += __shfl_down_sync(0xffffffffu, l1, o);
    }
    if (lane == 0) {
        ob[w*2 + 0] = l0 + bclf[0];
        ob[w*2 + 1] = l1 + bclf[1];
    }
}

// ---------------- y + loss tail --------------------------------------------
__global__ void k_tail(const int* __restrict__ labels, float* __restrict__ ob) {
    int t = blockIdx.x*blockDim.x + threadIdx.x;
    if (t < XR)  ob[XR*2 + t] = (t < NV) ? (float)labels[t] : 1.f;
    if (t == XR) ob[XR*2 + XR] = g_scal[2];
}

// ---------------- launcher -------------------------------------------------
extern "C" void kernel_launch(void* const* d_in, const int* in_sizes, int n_in,
                              void* d_out, int out_size) {
    const float* feat     = (const float*)d_in[0];
    const float* adj      = (const float*)d_in[1];
    const int*   src      = (const int*)  d_in[2];
    const int*   dst      = (const int*)  d_in[3];
    const int*   labels   = (const int*)  d_in[4];
    const float* W_pool0  = (const float*)d_in[5];
    const float* b_pool0  = (const float*)d_in[6];
    const float* W_self0  = (const float*)d_in[7];
    const float* W_neigh0 = (const float*)d_in[8];
    const float* b0       = (const float*)d_in[9];
    const float* W_pool1  = (const float*)d_in[10];
    const float* b_pool1  = (const float*)d_in[11];
    const float* W_self1  = (const float*)d_in[12];
    const float* W_neigh1 = (const float*)d_in[13];
    const float* b1       = (const float*)d_in[14];
    const float* de_w     = (const float*)d_in[15];
    const float* W_conv   = (const float*)d_in[16];
    const float* W_clf    = (const float*)d_in[17];
    const float* b_clf    = (const float*)d_in[18];
    const float* gaps     = (const float*)d_in[19];
    int E = in_sizes[2];
    float* ob = (float*)d_out;

    float *p0, *hn0, *hh, *p1, *hn1, *xv, *ov;
    cudaGetSymbolAddress((void**)&p0,  g_p0);
    cudaGetSymbolAddress((void**)&hn0, g_hn0);
    cudaGetSymbolAddress((void**)&hh,  g_h);
    cudaGetSymbolAddress((void**)&p1,  g_p1);
    cudaGetSymbolAddress((void**)&hn1, g_hn1);
    cudaGetSymbolAddress((void**)&xv,  g_x);
    cudaGetSymbolAddress((void**)&ov,  g_out);

    dim3 tb(16, 16);

    k_init<<<1024, 256>>>();

    // layer 0
    k_sgemm<<<dim3(FIN/32, NV/32), tb>>>(feat, W_pool0, b_pool0, p0, NV, FIN, FIN, 0, 1);
    {
        int tot = E * (FIN/4);
        k_scatter_max<<<(tot + 255)/256, 256>>>(p0, src, dst, hn0, E, FIN);
    }
    k_sgemm<<<dim3(HH/32, NV/32), tb>>>(feat, W_self0,  (const float*)0, hh, NV, HH, FIN, 0, 0);
    k_sgemm<<<dim3(HH/32, NV/32), tb>>>(hn0,  W_neigh0, b0,              hh, NV, HH, FIN, 1, 0);
    k_relu_l2norm<<<NV, HH>>>(hh);

    // layer 1
    k_sgemm<<<dim3(HH/32, NV/32), tb>>>(hh, W_pool1, b_pool1, p1, NV, HH, HH, 0, 1);
    {
        int tot = E * (HH/4);
        k_scatter_max<<<(tot + 255)/256, 256>>>(p1, src, dst, hn1, E, HH);
    }
    k_sgemm<<<dim3(HH/32, NV/32), tb>>>(hh,  W_self1,  (const float*)0, xv, NV, HH, HH, 0, 0);
    k_sgemm<<<dim3(HH/32, NV/32), tb>>>(hn1, W_neigh1, b1,              xv, NV, HH, HH, 1, 0);

    // SMOTE
    k_sq<<<MINC, HH>>>();
    k_smote<<<MINC, HH>>>(gaps);

    // decoder input
    k_sgemm<<<dim3(HH/32, XR/32), tb>>>(xv, de_w, (const float*)0, ov, XR, HH, HH, 0, 0);

    // edge count + neg weight
    k_count<<<2048, 256>>>(adj);
    k_negw<<<1, 1>>>();

    // big fused pass
    k_fused<<<XR/32, 256>>>(adj);

    // classifier
    k_weff<<<2, 256>>>(W_clf, W_conv);
    k_final<<<XR/4, 128>>>(b_clf, ob);
    k_tail<<<(XR + 256)/256 + 1, 256>>>(labels, ob);
}

// round 2
// speedup vs baseline: 4.6890x; 4.6890x over previous
#include <cuda_runtime.h>
#include <math.h>

#define NV    4096
#define FIN   256
#define HH    128
#define MINC  1024
#define REPC  2
#define XR    6144   // NV + MINC*REPC
#define NCH   4      // j-chunks in fused pass
#define CHJ   (XR/NCH)   // 1536

// ---------------- scratch (static __device__, no allocs) ----------------
__device__ __align__(16) float g_p0 [NV*FIN];
__device__ __align__(16) float g_hn0[NV*FIN];
__device__ __align__(16) float g_h  [NV*HH];
__device__ __align__(16) float g_p1 [NV*HH];
__device__ __align__(16) float g_hn1[NV*HH];
__device__ __align__(16) float g_x  [XR*HH];
__device__ __align__(16) float g_out[XR*HH];
__device__ __align__(16) float g_ng4[(size_t)NCH*XR*HH];
__device__ __align__(16) float g_rs4[NCH*XR];
__device__ __align__(16) float g_sq [MINC];
__device__ __align__(16) float g_scal[4];     // 0: edge count, 1: neg_w, 2: loss
__device__ __align__(16) float g_weff[2*256];

// ---------------- init: zero segment-max buffers + scalars ----------------
__global__ void k_init() {
    int i = blockIdx.x*blockDim.x + threadIdx.x;
    int T = gridDim.x*blockDim.x;
    for (int t = i; t < NV*FIN; t += T) g_hn0[t] = 0.f;
    for (int t = i; t < NV*HH;  t += T) g_hn1[t] = 0.f;
    if (i == 0) { g_scal[0] = 0.f; g_scal[2] = 0.f; }
}

// ---------------- generic C = A @ B^T (+bias) (+=) (relu) ----------------
__global__ void k_sgemm(const float* __restrict__ A, const float* __restrict__ B,
                        const float* __restrict__ bias, float* __restrict__ C,
                        int M, int N, int K, int acc, int dorelu) {
    __shared__ float As[32][33];
    __shared__ float Bs[32][33];
    int tx = threadIdx.x, ty = threadIdx.y;
    int lin = ty*16 + tx;
    int m0 = blockIdx.y*32, n0 = blockIdx.x*32;
    float c00=0.f,c01=0.f,c10=0.f,c11=0.f;
    int lr = lin >> 3, lc = (lin & 7) << 2;
    for (int k0 = 0; k0 < K; k0 += 32) {
        float4 av = *(const float4*)&A[(size_t)(m0+lr)*K + k0 + lc];
        As[lr][lc]=av.x; As[lr][lc+1]=av.y; As[lr][lc+2]=av.z; As[lr][lc+3]=av.w;
        float4 bv = *(const float4*)&B[(size_t)(n0+lr)*K + k0 + lc];
        Bs[lr][lc]=bv.x; Bs[lr][lc+1]=bv.y; Bs[lr][lc+2]=bv.z; Bs[lr][lc+3]=bv.w;
        __syncthreads();
        #pragma unroll
        for (int kk = 0; kk < 32; kk++) {
            float a0 = As[ty*2][kk],   a1 = As[ty*2+1][kk];
            float b0 = Bs[tx*2][kk],   b1 = Bs[tx*2+1][kk];
            c00 += a0*b0; c01 += a0*b1; c10 += a1*b0; c11 += a1*b1;
        }
        __syncthreads();
    }
    int m = m0 + ty*2, n = n0 + tx*2;
    float bb0 = bias ? bias[n]   : 0.f;
    float bb1 = bias ? bias[n+1] : 0.f;
    float o00 = c00+bb0, o01 = c01+bb1, o10 = c10+bb0, o11 = c11+bb1;
    if (acc) {
        o00 += C[(size_t)m*N+n];     o01 += C[(size_t)m*N+n+1];
        o10 += C[(size_t)(m+1)*N+n]; o11 += C[(size_t)(m+1)*N+n+1];
    }
    if (dorelu) {
        o00 = fmaxf(o00,0.f); o01 = fmaxf(o01,0.f);
        o10 = fmaxf(o10,0.f); o11 = fmaxf(o11,0.f);
    }
    C[(size_t)m*N+n]     = o00; C[(size_t)m*N+n+1]     = o01;
    C[(size_t)(m+1)*N+n] = o10; C[(size_t)(m+1)*N+n+1] = o11;
}

// ---------------- segment max via atomicMax on int bits (values >= 0) ------
__global__ void k_scatter_max(const float* __restrict__ p, const int* __restrict__ src,
                              const int* __restrict__ dst, float* __restrict__ hn,
                              int E, int F) {
    int nc = F >> 2;
    int tid = blockIdx.x*blockDim.x + threadIdx.x;
    if (tid >= E*nc) return;
    int e = tid / nc, c = (tid - e*nc) << 2;
    int s = src[e], d = dst[e];
    float4 v = *(const float4*)&p[(size_t)s*F + c];
    int* o = (int*)&hn[(size_t)d*F + c];
    atomicMax(o+0, __float_as_int(v.x));
    atomicMax(o+1, __float_as_int(v.y));
    atomicMax(o+2, __float_as_int(v.z));
    atomicMax(o+3, __float_as_int(v.w));
}

// ---------------- relu + row l2norm (H=128) --------------------------------
__global__ void k_relu_l2norm(float* __restrict__ h) {
    int r = blockIdx.x, t = threadIdx.x;
    float v = fmaxf(h[r*HH + t], 0.f);
    float s = v*v;
    #pragma unroll
    for (int o = 16; o; o >>= 1) s += __shfl_down_sync(0xffffffffu, s, o);
    __shared__ float ws[4];
    if ((t & 31) == 0) ws[t >> 5] = s;
    __syncthreads();
    float tot = ws[0] + ws[1] + ws[2] + ws[3];
    float nrm = fmaxf(sqrtf(tot), 1e-12f);
    h[r*HH + t] = v / nrm;
}

// ---------------- per-row squared norms of candidates ----------------------
__global__ void k_sq() {
    int r = blockIdx.x, t = threadIdx.x;
    float v = g_x[r*HH + t];
    float s = v*v;
    #pragma unroll
    for (int o = 16; o; o >>= 1) s += __shfl_down_sync(0xffffffffu, s, o);
    __shared__ float ws[4];
    if ((t & 31) == 0) ws[t >> 5] = s;
    __syncthreads();
    if (t == 0) g_sq[r] = ws[0] + ws[1] + ws[2] + ws[3];
}

// ---------------- SMOTE tiled: NN search + interpolation -------------------
// 32 blocks x 32 i-rows, 256 threads. smem-staged tiles, padded rows (33 slots).
__global__ void __launch_bounds__(256) k_smote2(const float* __restrict__ gaps) {
    __shared__ float4 ci[32*33];
    __shared__ float4 cj[32*33];
    __shared__ float  sqj[32];
    __shared__ int    snn[32];
    int t = threadIdx.x;
    int i0 = blockIdx.x*32;
    int ri = t >> 3, s = t & 7;

    const float4* srci = (const float4*)&g_x[(size_t)i0*HH];
    for (int l = t; l < 32*32; l += 256) {
        int r = l >> 5, kq = l & 31;
        ci[r*33 + kq] = srci[l];
    }
    __syncthreads();

    float sqi = g_sq[i0 + ri];
    int   gi  = i0 + ri;
    float best = 3.4e38f; int bestj = 0x7fffffff;

    for (int j0 = 0; j0 < MINC; j0 += 32) {
        __syncthreads();
        const float4* srcj = (const float4*)&g_x[(size_t)j0*HH];
        for (int l = t; l < 32*32; l += 256) {
            int r = l >> 5, kq = l & 31;
            cj[r*33 + kq] = srcj[l];
        }
        if (t < 32) sqj[t] = g_sq[j0 + t];
        __syncthreads();

        float d0=0.f,d1=0.f,d2=0.f,d3=0.f;
        #pragma unroll
        for (int kq = 0; kq < 32; kq++) {
            float4 a  = ci[ri*33 + kq];
            float4 b0 = cj[(s     )*33 + kq];
            float4 b1 = cj[(s +  8)*33 + kq];
            float4 b2 = cj[(s + 16)*33 + kq];
            float4 b3 = cj[(s + 24)*33 + kq];
            d0 += a.x*b0.x + a.y*b0.y + a.z*b0.z + a.w*b0.w;
            d1 += a.x*b1.x + a.y*b1.y + a.z*b1.z + a.w*b1.w;
            d2 += a.x*b2.x + a.y*b2.y + a.z*b2.z + a.w*b2.w;
            d3 += a.x*b3.x + a.y*b3.y + a.z*b3.z + a.w*b3.w;
        }
        float dd[4] = {d0,d1,d2,d3};
        #pragma unroll
        for (int m = 0; m < 4; m++) {
            int j = j0 + s + 8*m;
            float dv = sqi + sqj[s + 8*m] - 2.f*dd[m];
            if (j != gi) {
                if (dv < best || (dv == best && j < bestj)) { best = dv; bestj = j; }
            }
        }
    }
    #pragma unroll
    for (int o = 4; o; o >>= 1) {
        float ob = __shfl_down_sync(0xffffffffu, best, o);
        int   oj = __shfl_down_sync(0xffffffffu, bestj, o);
        if (ob < best || (ob == best && oj < bestj)) { best = ob; bestj = oj; }
    }
    if (s == 0) snn[ri] = bestj;
    __syncthreads();

    // interpolation: row r = t>>3, cols (t&7)*16 .. +15
    int r  = t >> 3;
    int c0 = (t & 7) * 16;
    int nn = snn[r];
    int gr = i0 + r;
    float ga = gaps[gr*REPC + 0], gb = gaps[gr*REPC + 1];
    #pragma unroll
    for (int u = 0; u < 16; u += 4) {
        float4 cv = ci[r*33 + ((c0 + u) >> 2)];
        float4 nv = *(const float4*)&g_x[(size_t)nn*HH + c0 + u];
        float4 oa, ob;
        oa.x = cv.x + ga*(nv.x - cv.x); oa.y = cv.y + ga*(nv.y - cv.y);
        oa.z = cv.z + ga*(nv.z - cv.z); oa.w = cv.w + ga*(nv.w - cv.w);
        ob.x = cv.x + gb*(nv.x - cv.x); ob.y = cv.y + gb*(nv.y - cv.y);
        ob.z = cv.z + gb*(nv.z - cv.z); ob.w = cv.w + gb*(nv.w - cv.w);
        *(float4*)&g_x[(size_t)(NV + 2*gr    )*HH + c0 + u] = oa;
        *(float4*)&g_x[(size_t)(NV + 2*gr + 1)*HH + c0 + u] = ob;
    }
}

// ---------------- count nonzero adj entries --------------------------------
__global__ void k_count(const float* __restrict__ adj) {
    int i = blockIdx.x*blockDim.x + threadIdx.x;
    int T = gridDim.x*blockDim.x;
    float c = 0.f;
    for (long t = i; t < (long)NV*NV; t += T) c += (adj[t] != 0.f) ? 1.f : 0.f;
    #pragma unroll
    for (int o = 16; o; o >>= 1) c += __shfl_down_sync(0xffffffffu, c, o);
    __shared__ float ws[8];
    int tt = threadIdx.x;
    if ((tt & 31) == 0) ws[tt >> 5] = c;
    __syncthreads();
    if (tt == 0) {
        float s = 0.f;
        for (int q = 0; q < (int)(blockDim.x >> 5); q++) s += ws[q];
        atomicAdd(&g_scal[0], s);
    }
}
__global__ void k_negw() {
    float e = g_scal[0];
    g_scal[1] = e / (16777216.f - e);
}

// ---------------- fused: gram -> sigmoid -> loss -> threshold -> neigh -----
// Block: 64 i-rows x one j-chunk (1536 j, 24 tiles of 64).
// Gram uses XOR-swizzled smem tiles (conflict-free 4x4 register blocking).
// x-tile is stored plain (its neigh access pattern is conflict-free).
__global__ void __launch_bounds__(256, 2) k_fused2(const float* __restrict__ adj) {
    extern __shared__ float4 dsm[];
    float4* soi = dsm;                       // 64*32 float4 (swizzled out_i)
    float4* sjt = dsm + 2048;                // 64*32 float4 (out_j swz / x_j plain)
    float*  Pt  = (float*)(dsm + 4096);      // [64][68] transposed thresholded P
    float*  lred = Pt + 64*68;

    int t  = threadIdx.x;
    int i0 = blockIdx.x * 64;
    int jbase = blockIdx.y * CHJ;

    int tx = t & 15, ty = t >> 4;            // gram mapping
    int hg = t & 15, ig = t >> 4;            // neigh mapping
    int sa = ty & 7, sb = tx & 7;

    // load swizzled i-tile
    {
        const float4* src = (const float4*)&g_out[(size_t)i0*HH];
        for (int l = t; l < 2048; l += 256) {
            int r = l >> 5, kq = l & 31;
            soi[r*32 + (kq ^ ((r >> 2) & 7))] = src[l];
        }
    }

    float nacc[32];
    #pragma unroll
    for (int q = 0; q < 32; q++) nacc[q] = 0.f;
    float rs0 = 0.f, rs1 = 0.f, rs2 = 0.f, rs3 = 0.f;
    float lloss = 0.f;
    float negw  = g_scal[1];
    bool  iin   = (i0 < NV);

    for (int jt = 0; jt < CHJ/64; jt++) {
        int j0 = jbase + jt*64;
        __syncthreads();   // protect sjt from previous neigh readers
        {
            const float4* srcj = (const float4*)&g_out[(size_t)j0*HH];
            for (int l = t; l < 2048; l += 256) {
                int r = l >> 5, kq = l & 31;
                sjt[r*32 + (kq ^ ((r >> 2) & 7))] = srcj[l];
            }
        }
        __syncthreads();

        // gram: thread computes P[i0+ty*4+q][j0+tx*4+p]
        float c[4][4];
        #pragma unroll
        for (int q = 0; q < 4; q++)
            #pragma unroll
            for (int p = 0; p < 4; p++) c[q][p] = 0.f;

        #pragma unroll 8
        for (int kq = 0; kq < 32; kq++) {
            float4 a0 = soi[(ty*4+0)*32 + (kq ^ sa)];
            float4 a1 = soi[(ty*4+1)*32 + (kq ^ sa)];
            float4 a2 = soi[(ty*4+2)*32 + (kq ^ sa)];
            float4 a3 = soi[(ty*4+3)*32 + (kq ^ sa)];
            float4 b0 = sjt[(tx*4+0)*32 + (kq ^ sb)];
            float4 b1 = sjt[(tx*4+1)*32 + (kq ^ sb)];
            float4 b2 = sjt[(tx*4+2)*32 + (kq ^ sb)];
            float4 b3 = sjt[(tx*4+3)*32 + (kq ^ sb)];
            c[0][0]+=a0.x*b0.x+a0.y*b0.y+a0.z*b0.z+a0.w*b0.w;
            c[0][1]+=a0.x*b1.x+a0.y*b1.y+a0.z*b1.z+a0.w*b1.w;
            c[0][2]+=a0.x*b2.x+a0.y*b2.y+a0.z*b2.z+a0.w*b2.w;
            c[0][3]+=a0.x*b3.x+a0.y*b3.y+a0.z*b3.z+a0.w*b3.w;
            c[1][0]+=a1.x*b0.x+a1.y*b0.y+a1.z*b0.z+a1.w*b0.w;
            c[1][1]+=a1.x*b1.x+a1.y*b1.y+a1.z*b1.z+a1.w*b1.w;
            c[1][2]+=a1.x*b2.x+a1.y*b2.y+a1.z*b2.z+a1.w*b2.w;
            c[1][3]+=a1.x*b3.x+a1.y*b3.y+a1.z*b3.z+a1.w*b3.w;
            c[2][0]+=a2.x*b0.x+a2.y*b0.y+a2.z*b0.z+a2.w*b0.w;
            c[2][1]+=a2.x*b1.x+a2.y*b1.y+a2.z*b1.z+a2.w*b1.w;
            c[2][2]+=a2.x*b2.x+a2.y*b2.y+a2.z*b2.z+a2.w*b2.w;
            c[2][3]+=a2.x*b3.x+a2.y*b3.y+a2.z*b3.z+a2.w*b3.w;
            c[3][0]+=a3.x*b0.x+a3.y*b0.y+a3.z*b0.z+a3.w*b0.w;
            c[3][1]+=a3.x*b1.x+a3.y*b1.y+a3.z*b1.z+a3.w*b1.w;
            c[3][2]+=a3.x*b2.x+a3.y*b2.y+a3.z*b2.z+a3.w*b2.w;
            c[3][3]+=a3.x*b3.x+a3.y*b3.y+a3.z*b3.z+a3.w*b3.w;
        }

        bool jin = (j0 < NV);
        bool doloss = iin && jin;
        #pragma unroll
        for (int q = 0; q < 4; q++) {
            int gi = i0 + ty*4 + q;
            float4 av;
            if (doloss) av = *(const float4*)&adj[(size_t)gi*NV + j0 + tx*4];
            #pragma unroll
            for (int p = 0; p < 4; p++) {
                float pv = 1.f / (1.f + __expf(-c[q][p]));
                if (doloss) {
                    float a_ = (&av.x)[p];
                    float w  = (a_ == 0.f) ? negw : 1.f;
                    float d  = pv - a_;
                    lloss += w*d*d;
                }
                Pt[(tx*4+p)*68 + ty*4 + q] = (pv >= 0.5f) ? pv : 0.f;
            }
        }
        __syncthreads();

        // load x-tile (plain layout) into sjt
        {
            const float4* srcx = (const float4*)&g_x[(size_t)j0*HH];
            for (int l = t; l < 2048; l += 256) sjt[l] = srcx[l];
        }
        __syncthreads();

        // neigh: thread covers rows ig*4..+3, cols hg*8..+7
        #pragma unroll 8
        for (int jj = 0; jj < 64; jj++) {
            float4 pf = *(const float4*)&Pt[jj*68 + ig*4];
            float4 x0 = sjt[jj*32 + hg*2];
            float4 x1 = sjt[jj*32 + hg*2 + 1];
            if (hg == 0) { rs0 += pf.x; rs1 += pf.y; rs2 += pf.z; rs3 += pf.w; }
            nacc[0] +=pf.x*x0.x; nacc[1] +=pf.x*x0.y; nacc[2] +=pf.x*x0.z; nacc[3] +=pf.x*x0.w;
            nacc[4] +=pf.x*x1.x; nacc[5] +=pf.x*x1.y; nacc[6] +=pf.x*x1.z; nacc[7] +=pf.x*x1.w;
            nacc[8] +=pf.y*x0.x; nacc[9] +=pf.y*x0.y; nacc[10]+=pf.y*x0.z; nacc[11]+=pf.y*x0.w;
            nacc[12]+=pf.y*x1.x; nacc[13]+=pf.y*x1.y; nacc[14]+=pf.y*x1.z; nacc[15]+=pf.y*x1.w;
            nacc[16]+=pf.z*x0.x; nacc[17]+=pf.z*x0.y; nacc[18]+=pf.z*x0.z; nacc[19]+=pf.z*x0.w;
            nacc[20]+=pf.z*x1.x; nacc[21]+=pf.z*x1.y; nacc[22]+=pf.z*x1.z; nacc[23]+=pf.z*x1.w;
            nacc[24]+=pf.w*x0.x; nacc[25]+=pf.w*x0.y; nacc[26]+=pf.w*x0.z; nacc[27]+=pf.w*x0.w;
            nacc[28]+=pf.w*x1.x; nacc[29]+=pf.w*x1.y; nacc[30]+=pf.w*x1.z; nacc[31]+=pf.w*x1.w;
        }
    }

    // write per-chunk partials (exclusive ownership -> plain stores)
    size_t cb = (size_t)blockIdx.y * XR;
    #pragma unroll
    for (int q = 0; q < 4; q++) {
        int gi = i0 + ig*4 + q;
        float* dst = &g_ng4[(cb + gi)*HH + hg*8];
        float4 v0 = make_float4(nacc[q*8+0], nacc[q*8+1], nacc[q*8+2], nacc[q*8+3]);
        float4 v1 = make_float4(nacc[q*8+4], nacc[q*8+5], nacc[q*8+6], nacc[q*8+7]);
        *(float4*)dst       = v0;
        *(float4*)(dst + 4) = v1;
    }
    if (hg == 0) {
        int gi = i0 + ig*4;
        g_rs4[cb + gi + 0] = rs0;
        g_rs4[cb + gi + 1] = rs1;
        g_rs4[cb + gi + 2] = rs2;
        g_rs4[cb + gi + 3] = rs3;
    }

    // loss reduction
    #pragma unroll
    for (int o = 16; o; o >>= 1) lloss += __shfl_down_sync(0xffffffffu, lloss, o);
    if ((t & 31) == 0) lred[t >> 5] = lloss;
    __syncthreads();
    if (t == 0) {
        float s = 0.f;
        for (int q = 0; q < 8; q++) s += lred[q];
        atomicAdd(&g_scal[2], s);
    }
}

// ---------------- W_eff = W_clf @ W_conv  [2,256] --------------------------
__global__ void k_weff(const float* __restrict__ Wclf, const float* __restrict__ Wconv) {
    int t = blockIdx.x*blockDim.x + threadIdx.x;
    if (t >= 512) return;
    int c = t >> 8, k = t & 255;
    float s = 0.f;
    for (int o = 0; o < HH; o++) s += Wclf[c*HH + o] * Wconv[o*256 + k];
    g_weff[c*256 + k] = s;
}

// ---------------- logits: warp per row -------------------------------------
__global__ void k_final(const float* __restrict__ bclf, float* __restrict__ ob) {
    int w = (blockIdx.x*blockDim.x + threadIdx.x) >> 5;
    int lane = threadIdx.x & 31;
    if (w >= XR) return;
    float rs = g_rs4[w] + g_rs4[XR + w] + g_rs4[2*XR + w] + g_rs4[3*XR + w];
    float inv = 1.f / (rs + 1.f);
    float l0 = 0.f, l1 = 0.f;
    for (int k = lane; k < HH; k += 32) {
        float xv = g_x[(size_t)w*HH + k];
        float nv = (g_ng4[(size_t)w*HH + k] + g_ng4[((size_t)XR + w)*HH + k]
                  + g_ng4[((size_t)2*XR + w)*HH + k] + g_ng4[((size_t)3*XR + w)*HH + k]) * inv;
        l0 += xv*g_weff[k]       + nv*g_weff[128 + k];
        l1 += xv*g_weff[256 + k] + nv*g_weff[256 + 128 + k];
    }
    #pragma unroll
    for (int o = 16; o; o >>= 1) {
        l0 += __shfl_down_sync(0xffffffffu, l0, o);
        l1 += __shfl_down_sync(0xffffffffu, l1, o);
    }
    if (lane == 0) {
        ob[w*2 + 0] = l0 + bclf[0];
        ob[w*2 + 1] = l1 + bclf[1];
    }
}

// ---------------- y + loss tail --------------------------------------------
__global__ void k_tail(const int* __restrict__ labels, float* __restrict__ ob) {
    int t = blockIdx.x*blockDim.x + threadIdx.x;
    if (t < XR)  ob[XR*2 + t] = (t < NV) ? (float)labels[t] : 1.f;
    if (t == XR) ob[XR*2 + XR] = g_scal[2];
}

// ---------------- launcher -------------------------------------------------
extern "C" void kernel_launch(void* const* d_in, const int* in_sizes, int n_in,
                              void* d_out, int out_size) {
    const float* feat     = (const float*)d_in[0];
    const float* adj      = (const float*)d_in[1];
    const int*   src      = (const int*)  d_in[2];
    const int*   dst      = (const int*)  d_in[3];
    const int*   labels   = (const int*)  d_in[4];
    const float* W_pool0  = (const float*)d_in[5];
    const float* b_pool0  = (const float*)d_in[6];
    const float* W_self0  = (const float*)d_in[7];
    const float* W_neigh0 = (const float*)d_in[8];
    const float* b0       = (const float*)d_in[9];
    const float* W_pool1  = (const float*)d_in[10];
    const float* b_pool1  = (const float*)d_in[11];
    const float* W_self1  = (const float*)d_in[12];
    const float* W_neigh1 = (const float*)d_in[13];
    const float* b1       = (const float*)d_in[14];
    const float* de_w     = (const float*)d_in[15];
    const float* W_conv   = (const float*)d_in[16];
    const float* W_clf    = (const float*)d_in[17];
    const float* b_clf    = (const float*)d_in[18];
    const float* gaps     = (const float*)d_in[19];
    int E = in_sizes[2];
    float* ob = (float*)d_out;

    float *p0, *hn0, *hh, *p1, *hn1, *xv, *ov;
    cudaGetSymbolAddress((void**)&p0,  g_p0);
    cudaGetSymbolAddress((void**)&hn0, g_hn0);
    cudaGetSymbolAddress((void**)&hh,  g_h);
    cudaGetSymbolAddress((void**)&p1,  g_p1);
    cudaGetSymbolAddress((void**)&hn1, g_hn1);
    cudaGetSymbolAddress((void**)&xv,  g_x);
    cudaGetSymbolAddress((void**)&ov,  g_out);

    const int FUSED_SMEM = 4096*16 + 64*68*4 + 32;   // 82976 bytes
    cudaFuncSetAttribute(k_fused2, cudaFuncAttributeMaxDynamicSharedMemorySize, FUSED_SMEM);

    dim3 tb(16, 16);

    k_init<<<1024, 256>>>();

    // layer 0
    k_sgemm<<<dim3(FIN/32, NV/32), tb>>>(feat, W_pool0, b_pool0, p0, NV, FIN, FIN, 0, 1);
    {
        int tot = E * (FIN/4);
        k_scatter_max<<<(tot + 255)/256, 256>>>(p0, src, dst, hn0, E, FIN);
    }
    k_sgemm<<<dim3(HH/32, NV/32), tb>>>(feat, W_self0,  (const float*)0, hh, NV, HH, FIN, 0, 0);
    k_sgemm<<<dim3(HH/32, NV/32), tb>>>(hn0,  W_neigh0, b0,              hh, NV, HH, FIN, 1, 0);
    k_relu_l2norm<<<NV, HH>>>(hh);

    // layer 1
    k_sgemm<<<dim3(HH/32, NV/32), tb>>>(hh, W_pool1, b_pool1, p1, NV, HH, HH, 0, 1);
    {
        int tot = E * (HH/4);
        k_scatter_max<<<(tot + 255)/256, 256>>>(p1, src, dst, hn1, E, HH);
    }
    k_sgemm<<<dim3(HH/32, NV/32), tb>>>(hh,  W_self1,  (const float*)0, xv, NV, HH, HH, 0, 0);
    k_sgemm<<<dim3(HH/32, NV/32), tb>>>(hn1, W_neigh1, b1,              xv, NV, HH, HH, 1, 0);

    // SMOTE
    k_sq<<<MINC, HH>>>();
    k_smote2<<<MINC/32, 256>>>(gaps);

    // decoder input (needs synth rows, so after smote)
    k_sgemm<<<dim3(HH/32, XR/32), tb>>>(xv, de_w, (const float*)0, ov, XR, HH, HH, 0, 0);

    // edge count + neg weight
    k_count<<<2048, 256>>>(adj);
    k_negw<<<1, 1>>>();

    // big fused pass
    k_fused2<<<dim3(XR/64, NCH), 256, FUSED_SMEM>>>(adj);

    // classifier
    k_weff<<<2, 256>>>(W_clf, W_conv);
    k_final<<<XR/4, 128>>>(b_clf, ob);
    k_tail<<<(XR + 256)/256 + 1, 256>>>(labels, ob);
}

// round 4
// speedup vs baseline: 10.5408x; 2.2480x over previous
#include <cuda_runtime.h>
#include <math.h>

#define NV    4096
#define FIN   256
#define HH    128
#define MINC  1024
#define REPC  2
#define XR    6144   // NV + MINC*REPC
#define NCH   3      // j-chunks in fused pass
#define CHJ   (XR/NCH)   // 2048

// ---------------- scratch (static __device__, no allocs) ----------------
__device__ __align__(16) float g_p0 [NV*FIN];
__device__ __align__(16) float g_hn0[NV*FIN];
__device__ __align__(16) float g_h  [NV*HH];
__device__ __align__(16) float g_p1 [NV*HH];
__device__ __align__(16) float g_hn1[NV*HH];
__device__ __align__(16) float g_x  [XR*HH];
__device__ __align__(16) float g_xt [HH*XR];          // transposed + tf32-rounded
__device__ __align__(16) float g_out[XR*HH];
__device__ __align__(16) float g_ng4[(size_t)NCH*XR*HH];
__device__ __align__(16) float g_rs4[NCH*XR];
__device__ __align__(16) float g_sq [MINC];
__device__ __align__(16) float g_scal[4];     // 0: edge count, 1: neg_w, 2: loss
__device__ __align__(16) float g_weff[2*256];

__device__ __forceinline__ float tf32r(float x) {
    unsigned u;
    asm("cvt.rna.tf32.f32 %0, %1;" : "=r"(u) : "f"(x));
    return __uint_as_float(u);
}

__device__ __forceinline__ void mma8(float* d, unsigned a0, unsigned a1, unsigned a2,
                                     unsigned a3, unsigned b0, unsigned b1) {
    asm volatile("mma.sync.aligned.m16n8k8.row.col.f32.tf32.tf32.f32 "
                 "{%0,%1,%2,%3}, {%4,%5,%6,%7}, {%8,%9}, {%0,%1,%2,%3};"
                 : "+f"(d[0]), "+f"(d[1]), "+f"(d[2]), "+f"(d[3])
                 : "r"(a0), "r"(a1), "r"(a2), "r"(a3), "r"(b0), "r"(b1));
}

// ---------------- init ------------------------------------------------------
__global__ void k_init() {
    int i = blockIdx.x*blockDim.x + threadIdx.x;
    int T = gridDim.x*blockDim.x;
    for (int t = i; t < NV*FIN; t += T) g_hn0[t] = 0.f;
    for (int t = i; t < NV*HH;  t += T) g_hn1[t] = 0.f;
    if (i == 0) { g_scal[0] = 0.f; g_scal[2] = 0.f; }
}

// ---------------- generic C = A @ B^T (+bias) (+=) (relu) -------------------
__global__ void k_sgemm(const float* __restrict__ A, const float* __restrict__ B,
                        const float* __restrict__ bias, float* __restrict__ C,
                        int M, int N, int K, int acc, int dorelu) {
    __shared__ float As[32][33];
    __shared__ float Bs[32][33];
    int tx = threadIdx.x, ty = threadIdx.y;
    int lin = ty*16 + tx;
    int m0 = blockIdx.y*32, n0 = blockIdx.x*32;
    float c00=0.f,c01=0.f,c10=0.f,c11=0.f;
    int lr = lin >> 3, lc = (lin & 7) << 2;
    for (int k0 = 0; k0 < K; k0 += 32) {
        float4 av = *(const float4*)&A[(size_t)(m0+lr)*K + k0 + lc];
        As[lr][lc]=av.x; As[lr][lc+1]=av.y; As[lr][lc+2]=av.z; As[lr][lc+3]=av.w;
        float4 bv = *(const float4*)&B[(size_t)(n0+lr)*K + k0 + lc];
        Bs[lr][lc]=bv.x; Bs[lr][lc+1]=bv.y; Bs[lr][lc+2]=bv.z; Bs[lr][lc+3]=bv.w;
        __syncthreads();
        #pragma unroll
        for (int kk = 0; kk < 32; kk++) {
            float a0 = As[ty*2][kk],   a1 = As[ty*2+1][kk];
            float b0 = Bs[tx*2][kk],   b1 = Bs[tx*2+1][kk];
            c00 += a0*b0; c01 += a0*b1; c10 += a1*b0; c11 += a1*b1;
        }
        __syncthreads();
    }
    int m = m0 + ty*2, n = n0 + tx*2;
    float bb0 = bias ? bias[n]   : 0.f;
    float bb1 = bias ? bias[n+1] : 0.f;
    float o00 = c00+bb0, o01 = c01+bb1, o10 = c10+bb0, o11 = c11+bb1;
    if (acc) {
        o00 += C[(size_t)m*N+n];     o01 += C[(size_t)m*N+n+1];
        o10 += C[(size_t)(m+1)*N+n]; o11 += C[(size_t)(m+1)*N+n+1];
    }
    if (dorelu) {
        o00 = fmaxf(o00,0.f); o01 = fmaxf(o01,0.f);
        o10 = fmaxf(o10,0.f); o11 = fmaxf(o11,0.f);
    }
    C[(size_t)m*N+n]     = o00; C[(size_t)m*N+n+1]     = o01;
    C[(size_t)(m+1)*N+n] = o10; C[(size_t)(m+1)*N+n+1] = o11;
}

// ---------------- segment max via atomicMax on int bits ---------------------
__global__ void k_scatter_max(const float* __restrict__ p, const int* __restrict__ src,
                              const int* __restrict__ dst, float* __restrict__ hn,
                              int E, int F) {
    int nc = F >> 2;
    int tid = blockIdx.x*blockDim.x + threadIdx.x;
    if (tid >= E*nc) return;
    int e = tid / nc, c = (tid - e*nc) << 2;
    int s = src[e], d = dst[e];
    float4 v = *(const float4*)&p[(size_t)s*F + c];
    int* o = (int*)&hn[(size_t)d*F + c];
    atomicMax(o+0, __float_as_int(v.x));
    atomicMax(o+1, __float_as_int(v.y));
    atomicMax(o+2, __float_as_int(v.z));
    atomicMax(o+3, __float_as_int(v.w));
}

// ---------------- relu + row l2norm -----------------------------------------
__global__ void k_relu_l2norm(float* __restrict__ h) {
    int r = blockIdx.x, t = threadIdx.x;
    float v = fmaxf(h[r*HH + t], 0.f);
    float s = v*v;
    #pragma unroll
    for (int o = 16; o; o >>= 1) s += __shfl_down_sync(0xffffffffu, s, o);
    __shared__ float ws[4];
    if ((t & 31) == 0) ws[t >> 5] = s;
    __syncthreads();
    float tot = ws[0] + ws[1] + ws[2] + ws[3];
    float nrm = fmaxf(sqrtf(tot), 1e-12f);
    h[r*HH + t] = v / nrm;
}

// ---------------- per-row squared norms -------------------------------------
__global__ void k_sq() {
    int r = blockIdx.x, t = threadIdx.x;
    float v = g_x[r*HH + t];
    float s = v*v;
    #pragma unroll
    for (int o = 16; o; o >>= 1) s += __shfl_down_sync(0xffffffffu, s, o);
    __shared__ float ws[4];
    if ((t & 31) == 0) ws[t >> 5] = s;
    __syncthreads();
    if (t == 0) g_sq[r] = ws[0] + ws[1] + ws[2] + ws[3];
}

// ---------------- SMOTE tiled -----------------------------------------------
__global__ void __launch_bounds__(256) k_smote2(const float* __restrict__ gaps) {
    __shared__ float4 ci[32*33];
    __shared__ float4 cj[32*33];
    __shared__ float  sqj[32];
    __shared__ int    snn[32];
    int t = threadIdx.x;
    int i0 = blockIdx.x*32;
    int ri = t >> 3, s = t & 7;

    const float4* srci = (const float4*)&g_x[(size_t)i0*HH];
    for (int l = t; l < 32*32; l += 256) {
        int r = l >> 5, kq = l & 31;
        ci[r*33 + kq] = srci[l];
    }
    __syncthreads();

    float sqi = g_sq[i0 + ri];
    int   gi  = i0 + ri;
    float best = 3.4e38f; int bestj = 0x7fffffff;

    for (int j0 = 0; j0 < MINC; j0 += 32) {
        __syncthreads();
        const float4* srcj = (const float4*)&g_x[(size_t)j0*HH];
        for (int l = t; l < 32*32; l += 256) {
            int r = l >> 5, kq = l & 31;
            cj[r*33 + kq] = srcj[l];
        }
        if (t < 32) sqj[t] = g_sq[j0 + t];
        __syncthreads();

        float d0=0.f,d1=0.f,d2=0.f,d3=0.f;
        #pragma unroll
        for (int kq = 0; kq < 32; kq++) {
            float4 a  = ci[ri*33 + kq];
            float4 b0 = cj[(s     )*33 + kq];
            float4 b1 = cj[(s +  8)*33 + kq];
            float4 b2 = cj[(s + 16)*33 + kq];
            float4 b3 = cj[(s + 24)*33 + kq];
            d0 += a.x*b0.x + a.y*b0.y + a.z*b0.z + a.w*b0.w;
            d1 += a.x*b1.x + a.y*b1.y + a.z*b1.z + a.w*b1.w;
            d2 += a.x*b2.x + a.y*b2.y + a.z*b2.z + a.w*b2.w;
            d3 += a.x*b3.x + a.y*b3.y + a.z*b3.z + a.w*b3.w;
        }
        float dd[4] = {d0,d1,d2,d3};
        #pragma unroll
        for (int m = 0; m < 4; m++) {
            int j = j0 + s + 8*m;
            float dv = sqi + sqj[s + 8*m] - 2.f*dd[m];
            if (j != gi) {
                if (dv < best || (dv == best && j < bestj)) { best = dv; bestj = j; }
            }
        }
    }
    #pragma unroll
    for (int o = 4; o; o >>= 1) {
        float ob = __shfl_down_sync(0xffffffffu, best, o);
        int   oj = __shfl_down_sync(0xffffffffu, bestj, o);
        if (ob < best || (ob == best && oj < bestj)) { best = ob; bestj = oj; }
    }
    if (s == 0) snn[ri] = bestj;
    __syncthreads();

    int r  = t >> 3;
    int c0 = (t & 7) * 16;
    int nn = snn[r];
    int gr = i0 + r;
    float ga = gaps[gr*REPC + 0], gb = gaps[gr*REPC + 1];
    #pragma unroll
    for (int u = 0; u < 16; u += 4) {
        float4 cv = ci[r*33 + ((c0 + u) >> 2)];
        float4 nv = *(const float4*)&g_x[(size_t)nn*HH + c0 + u];
        float4 oa, ob;
        oa.x = cv.x + ga*(nv.x - cv.x); oa.y = cv.y + ga*(nv.y - cv.y);
        oa.z = cv.z + ga*(nv.z - cv.z); oa.w = cv.w + ga*(nv.w - cv.w);
        ob.x = cv.x + gb*(nv.x - cv.x); ob.y = cv.y + gb*(nv.y - cv.y);
        ob.z = cv.z + gb*(nv.z - cv.z); ob.w = cv.w + gb*(nv.w - cv.w);
        *(float4*)&g_x[(size_t)(NV + 2*gr    )*HH + c0 + u] = oa;
        *(float4*)&g_x[(size_t)(NV + 2*gr + 1)*HH + c0 + u] = ob;
    }
}

// ---------------- count nonzero adj entries ---------------------------------
__global__ void k_count(const float* __restrict__ adj) {
    int i = blockIdx.x*blockDim.x + threadIdx.x;
    int T = gridDim.x*blockDim.x;
    float c = 0.f;
    for (long t = i; t < (long)NV*NV; t += T) c += (adj[t] != 0.f) ? 1.f : 0.f;
    #pragma unroll
    for (int o = 16; o; o >>= 1) c += __shfl_down_sync(0xffffffffu, c, o);
    __shared__ float ws[8];
    int tt = threadIdx.x;
    if ((tt & 31) == 0) ws[tt >> 5] = c;
    __syncthreads();
    if (tt == 0) {
        float s = 0.f;
        for (int q = 0; q < (int)(blockDim.x >> 5); q++) s += ws[q];
        atomicAdd(&g_scal[0], s);
    }
}
__global__ void k_negw() {
    float e = g_scal[0];
    g_scal[1] = e / (16777216.f - e);
}

// ---------------- prep: round g_out to tf32; build g_xt (T + rounded) -------
__global__ void k_round_out() {
    int i = blockIdx.x*blockDim.x + threadIdx.x;    // 196608 float4
    float4 v = ((const float4*)g_out)[i];
    v.x = tf32r(v.x); v.y = tf32r(v.y); v.z = tf32r(v.z); v.w = tf32r(v.w);
    ((float4*)g_out)[i] = v;
}
__global__ void k_xt() {
    __shared__ float tl[32][33];
    int j0 = blockIdx.x*32, h0 = blockIdx.y*32;
    int tx = threadIdx.x, ty = threadIdx.y;  // (32,8)
    #pragma unroll
    for (int q = 0; q < 32; q += 8)
        tl[ty+q][tx] = g_x[(size_t)(j0+ty+q)*HH + h0 + tx];
    __syncthreads();
    #pragma unroll
    for (int q = 0; q < 32; q += 8)
        g_xt[(size_t)(h0+ty+q)*XR + j0 + tx] = tf32r(tl[tx][ty+q]);
}

// ---------------- fused tf32-MMA: gram -> sigmoid -> loss -> thresh -> neigh
// Block: 64 i x 64 j tiles over a 2048-j chunk. 8 warps: wi=warp>>1 (16 i-rows),
// wj=warp&1 (32 j-cols for gram / 64 h-cols for neigh).
__global__ void __launch_bounds__(256, 2) k_fused3(const float* __restrict__ adj) {
    extern __shared__ float dsm[];
    float* soi = dsm;                    // [64][132] out_i (tf32-rounded fp32)
    float* buf = dsm + 64*132;           // union: out_j [64][132] / xT [128][68]
    float* sp  = buf + 128*68;           // [64][68] thresholded P (tf32)
    float* srs = sp + 64*68;             // [2][64] rowsum partials
    float* lred = srs + 128;             // [8]

    int t    = threadIdx.x;
    int lane = t & 31, warp = t >> 5;
    int wi = warp >> 1, wj = warp & 1;
    int g  = lane >> 2, c = lane & 3;
    int i0 = blockIdx.x * 64;
    int chunk = blockIdx.y;
    int jbase = chunk * CHJ;
    bool lossi = (i0 < NV) && (chunk < 2);

    // load i-tile once (row stride 132 floats = 33 float4)
    {
        const float4* src = (const float4*)&g_out[(size_t)i0*HH];
        float4* dstq = (float4*)soi;
        for (int l = t; l < 2048; l += 256) {
            int r = l >> 5, kq = l & 31;
            dstq[r*33 + kq] = src[l];
        }
    }

    float nacc[8][4];
    #pragma unroll
    for (int nt = 0; nt < 8; nt++)
        #pragma unroll
        for (int q = 0; q < 4; q++) nacc[nt][q] = 0.f;
    float rsum0 = 0.f, rsum1 = 0.f, lloss = 0.f;
    float negw = g_scal[1];

    const float* Ab = soi + (wi*16)*132;
    const float* Pb = sp  + (wi*16)*68;

    for (int jt = 0; jt < CHJ/64; jt++) {
        int j0 = jbase + jt*64;
        __syncthreads();
        // load out_j tile [64][132]
        {
            const float4* src = (const float4*)&g_out[(size_t)j0*HH];
            float4* dstq = (float4*)buf;
            for (int l = t; l < 2048; l += 256) {
                int r = l >> 5, kq = l & 31;
                dstq[r*33 + kq] = src[l];
            }
        }
        __syncthreads();

        // ---- gram MMA: dg[nt] = out_i(16) x out_j(8 per nt), k=128 ----
        float dg[4][4];
        #pragma unroll
        for (int nt = 0; nt < 4; nt++)
            #pragma unroll
            for (int q = 0; q < 4; q++) dg[nt][q] = 0.f;
        const float* Bb = buf + (wj*32)*132;
        #pragma unroll 4
        for (int ks = 0; ks < 16; ks++) {
            int k = ks*8;
            unsigned a0 = __float_as_uint(Ab[(g    )*132 + k + c    ]);
            unsigned a1 = __float_as_uint(Ab[(g + 8)*132 + k + c    ]);
            unsigned a2 = __float_as_uint(Ab[(g    )*132 + k + c + 4]);
            unsigned a3 = __float_as_uint(Ab[(g + 8)*132 + k + c + 4]);
            #pragma unroll
            for (int nt = 0; nt < 4; nt++) {
                unsigned b0 = __float_as_uint(Bb[(nt*8 + g)*132 + k + c    ]);
                unsigned b1 = __float_as_uint(Bb[(nt*8 + g)*132 + k + c + 4]);
                mma8(dg[nt], a0, a1, a2, a3, b0, b1);
            }
        }

        // ---- epilogue: sigmoid, loss, rowsum, write thresholded P ----
        bool doloss = lossi;   // j0 < NV guaranteed for chunk<2
        #pragma unroll
        for (int nt = 0; nt < 4; nt++) {
            int lj = wj*32 + nt*8 + c*2;
            int gj = j0 + lj;
            int r0 = i0 + wi*16 + g, r1 = r0 + 8;
            float p0 = 1.f/(1.f + __expf(-dg[nt][0]));
            float p1 = 1.f/(1.f + __expf(-dg[nt][1]));
            float p2 = 1.f/(1.f + __expf(-dg[nt][2]));
            float p3 = 1.f/(1.f + __expf(-dg[nt][3]));
            if (doloss) {
                float2 a0v = *(const float2*)&adj[(size_t)r0*NV + gj];
                float2 a1v = *(const float2*)&adj[(size_t)r1*NV + gj];
                float w0 = (a0v.x == 0.f) ? negw : 1.f;
                float w1 = (a0v.y == 0.f) ? negw : 1.f;
                float w2 = (a1v.x == 0.f) ? negw : 1.f;
                float w3 = (a1v.y == 0.f) ? negw : 1.f;
                float e0 = p0 - a0v.x, e1 = p1 - a0v.y;
                float e2 = p2 - a1v.x, e3 = p3 - a1v.y;
                lloss += w0*e0*e0 + w1*e1*e1 + w2*e2*e2 + w3*e3*e3;
            }
            float t0 = (p0 >= 0.5f) ? p0 : 0.f;
            float t1 = (p1 >= 0.5f) ? p1 : 0.f;
            float t2 = (p2 >= 0.5f) ? p2 : 0.f;
            float t3 = (p3 >= 0.5f) ? p3 : 0.f;
            rsum0 += t0 + t1;  rsum1 += t2 + t3;
            *(float2*)&sp[(wi*16 + g    )*68 + lj] = make_float2(tf32r(t0), tf32r(t1));
            *(float2*)&sp[(wi*16 + g + 8)*68 + lj] = make_float2(tf32r(t2), tf32r(t3));
        }
        __syncthreads();   // sp complete; buf free

        // load xT tile [128][68]
        {
            const float* srcb = g_xt + j0;
            float4* dstq = (float4*)buf;
            for (int l = t; l < 2048; l += 256) {
                int h = l >> 4, q = l & 15;
                dstq[h*17 + q] = *(const float4*)&srcb[(size_t)h*XR + q*4];
            }
        }
        __syncthreads();

        // ---- neigh MMA: nacc += P(16 x 64j) x x(64j x 64h) ----
        #pragma unroll 2
        for (int ks = 0; ks < 8; ks++) {
            int k = ks*8;
            unsigned a0 = __float_as_uint(Pb[(g    )*68 + k + c    ]);
            unsigned a1 = __float_as_uint(Pb[(g + 8)*68 + k + c    ]);
            unsigned a2 = __float_as_uint(Pb[(g    )*68 + k + c + 4]);
            unsigned a3 = __float_as_uint(Pb[(g + 8)*68 + k + c + 4]);
            #pragma unroll
            for (int nt = 0; nt < 8; nt++) {
                unsigned b0 = __float_as_uint(buf[(wj*64 + nt*8 + g)*68 + k + c    ]);
                unsigned b1 = __float_as_uint(buf[(wj*64 + nt*8 + g)*68 + k + c + 4]);
                mma8(nacc[nt], a0, a1, a2, a3, b0, b1);
            }
        }
    }

    // ---- write neigh partials (exclusive per chunk) ----
    size_t cb = (size_t)chunk * XR;
    #pragma unroll
    for (int nt = 0; nt < 8; nt++) {
        int h = wj*64 + nt*8 + c*2;
        int r0 = i0 + wi*16 + g, r1 = r0 + 8;
        *(float2*)&g_ng4[(cb + r0)*HH + h] = make_float2(nacc[nt][0], nacc[nt][1]);
        *(float2*)&g_ng4[(cb + r1)*HH + h] = make_float2(nacc[nt][2], nacc[nt][3]);
    }

    // ---- rowsums: reduce over c (4 lanes), then over wj via smem ----
    #pragma unroll
    for (int o = 1; o <= 2; o <<= 1) {
        rsum0 += __shfl_xor_sync(0xffffffffu, rsum0, o);
        rsum1 += __shfl_xor_sync(0xffffffffu, rsum1, o);
    }
    if (c == 0) {
        srs[wj*64 + wi*16 + g    ] = rsum0;
        srs[wj*64 + wi*16 + g + 8] = rsum1;
    }
    // ---- loss ----
    #pragma unroll
    for (int o = 16; o; o >>= 1) lloss += __shfl_down_sync(0xffffffffu, lloss, o);
    if (lane == 0) lred[warp] = lloss;
    __syncthreads();
    if (t < 64) g_rs4[cb + i0 + t] = srs[t] + srs[64 + t];
    if (t == 0) {
        float s = 0.f;
        for (int q = 0; q < 8; q++) s += lred[q];
        atomicAdd(&g_scal[2], s);
    }
}

// ---------------- W_eff = W_clf @ W_conv  [2,256] ---------------------------
__global__ void k_weff(const float* __restrict__ Wclf, const float* __restrict__ Wconv) {
    int t = blockIdx.x*blockDim.x + threadIdx.x;
    if (t >= 512) return;
    int c = t >> 8, k = t & 255;
    float s = 0.f;
    for (int o = 0; o < HH; o++) s += Wclf[c*HH + o] * Wconv[o*256 + k];
    g_weff[c*256 + k] = s;
}

// ---------------- logits ----------------------------------------------------
__global__ void k_final(const float* __restrict__ bclf, float* __restrict__ ob) {
    int w = (blockIdx.x*blockDim.x + threadIdx.x) >> 5;
    int lane = threadIdx.x & 31;
    if (w >= XR) return;
    float rs = g_rs4[w] + g_rs4[XR + w] + g_rs4[2*XR + w];
    float inv = 1.f / (rs + 1.f);
    float l0 = 0.f, l1 = 0.f;
    for (int k = lane; k < HH; k += 32) {
        float xv = g_x[(size_t)w*HH + k];
        float nv = (g_ng4[(size_t)w*HH + k] + g_ng4[((size_t)XR + w)*HH + k]
                  + g_ng4[((size_t)2*XR + w)*HH + k]) * inv;
        l0 += xv*g_weff[k]       + nv*g_weff[128 + k];
        l1 += xv*g_weff[256 + k] + nv*g_weff[256 + 128 + k];
    }
    #pragma unroll
    for (int o = 16; o; o >>= 1) {
        l0 += __shfl_down_sync(0xffffffffu, l0, o);
        l1 += __shfl_down_sync(0xffffffffu, l1, o);
    }
    if (lane == 0) {
        ob[w*2 + 0] = l0 + bclf[0];
        ob[w*2 + 1] = l1 + bclf[1];
    }
}

// ---------------- y + loss tail ---------------------------------------------
__global__ void k_tail(const int* __restrict__ labels, float* __restrict__ ob) {
    int t = blockIdx.x*blockDim.x + threadIdx.x;
    if (t < XR)  ob[XR*2 + t] = (t < NV) ? (float)labels[t] : 1.f;
    if (t == XR) ob[XR*2 + XR] = g_scal[2];
}

// ---------------- launcher --------------------------------------------------
extern "C" void kernel_launch(void* const* d_in, const int* in_sizes, int n_in,
                              void* d_out, int out_size) {
    const float* feat     = (const float*)d_in[0];
    const float* adj      = (const float*)d_in[1];
    const int*   src      = (const int*)  d_in[2];
    const int*   dst      = (const int*)  d_in[3];
    const int*   labels   = (const int*)  d_in[4];
    const float* W_pool0  = (const float*)d_in[5];
    const float* b_pool0  = (const float*)d_in[6];
    const float* W_self0  = (const float*)d_in[7];
    const float* W_neigh0 = (const float*)d_in[8];
    const float* b0       = (const float*)d_in[9];
    const float* W_pool1  = (const float*)d_in[10];
    const float* b_pool1  = (const float*)d_in[11];
    const float* W_self1  = (const float*)d_in[12];
    const float* W_neigh1 = (const float*)d_in[13];
    const float* b1       = (const float*)d_in[14];
    const float* de_w     = (const float*)d_in[15];
    const float* W_conv   = (const float*)d_in[16];
    const float* W_clf    = (const float*)d_in[17];
    const float* b_clf    = (const float*)d_in[18];
    const float* gaps     = (const float*)d_in[19];
    int E = in_sizes[2];
    float* ob = (float*)d_out;

    float *p0, *hn0, *hh, *p1, *hn1, *xv, *ov;
    cudaGetSymbolAddress((void**)&p0,  g_p0);
    cudaGetSymbolAddress((void**)&hn0, g_hn0);
    cudaGetSymbolAddress((void**)&hh,  g_h);
    cudaGetSymbolAddress((void**)&p1,  g_p1);
    cudaGetSymbolAddress((void**)&hn1, g_hn1);
    cudaGetSymbolAddress((void**)&xv,  g_x);
    cudaGetSymbolAddress((void**)&ov,  g_out);

    const int FUSED_SMEM = (64*132 + 128*68 + 64*68 + 128 + 8) * 4;  // 86560 B
    cudaFuncSetAttribute(k_fused3, cudaFuncAttributeMaxDynamicSharedMemorySize, FUSED_SMEM);

    dim3 tb(16, 16);

    k_init<<<1024, 256>>>();

    // layer 0
    k_sgemm<<<dim3(FIN/32, NV/32), tb>>>(feat, W_pool0, b_pool0, p0, NV, FIN, FIN, 0, 1);
    {
        int tot = E * (FIN/4);
        k_scatter_max<<<(tot + 255)/256, 256>>>(p0, src, dst, hn0, E, FIN);
    }
    k_sgemm<<<dim3(HH/32, NV/32), tb>>>(feat, W_self0,  (const float*)0, hh, NV, HH, FIN, 0, 0);
    k_sgemm<<<dim3(HH/32, NV/32), tb>>>(hn0,  W_neigh0, b0,              hh, NV, HH, FIN, 1, 0);
    k_relu_l2norm<<<NV, HH>>>(hh);

    // layer 1
    k_sgemm<<<dim3(HH/32, NV/32), tb>>>(hh, W_pool1, b_pool1, p1, NV, HH, HH, 0, 1);
    {
        int tot = E * (HH/4);
        k_scatter_max<<<(tot + 255)/256, 256>>>(p1, src, dst, hn1, E, HH);
    }
    k_sgemm<<<dim3(HH/32, NV/32), tb>>>(hh,  W_self1,  (const float*)0, xv, NV, HH, HH, 0, 0);
    k_sgemm<<<dim3(HH/32, NV/32), tb>>>(hn1, W_neigh1, b1,              xv, NV, HH, HH, 1, 0);

    // SMOTE
    k_sq<<<MINC, HH>>>();
    k_smote2<<<MINC/32, 256>>>(gaps);

    // decoder input + tf32 prep
    k_sgemm<<<dim3(HH/32, XR/32), tb>>>(xv, de_w, (const float*)0, ov, XR, HH, HH, 0, 0);
    k_round_out<<<768, 256>>>();
    k_xt<<<dim3(XR/32, HH/32), dim3(32, 8)>>>();

    // edge count + neg weight
    k_count<<<2048, 256>>>(adj);
    k_negw<<<1, 1>>>();

    // big fused pass (tensor cores)
    k_fused3<<<dim3(XR/64, NCH), 256, FUSED_SMEM>>>(adj);

    // classifier
    k_weff<<<2, 256>>>(W_clf, W_conv);
    k_final<<<XR/4, 128>>>(b_clf, ob);
    k_tail<<<(XR + 256)/256 + 1, 256>>>(labels, ob);
}

// round 6
// speedup vs baseline: 11.8001x; 1.1195x over previous
#include <cuda_runtime.h>
#include <math.h>

#define NV    4096
#define FIN   256
#define HH    128
#define MINC  1024
#define REPC  2
#define XR    6144   // NV + MINC*REPC
#define NCH   3      // j-chunks in fused pass
#define CHJ   (XR/NCH)   // 2048
#define CAP   128    // per-node adjacency capacity (mean deg ~17)

// ---------------- scratch (static __device__, no allocs) ----------------
__device__ __align__(16) float g_p0 [NV*FIN];
__device__ __align__(16) float g_hn0[NV*FIN];
__device__ __align__(16) float g_h  [NV*HH];
__device__ __align__(16) float g_p1 [NV*HH];
__device__ __align__(16) float g_hn1[NV*HH];
__device__ __align__(16) float g_x  [XR*HH];
__device__ __align__(16) float g_xt [HH*XR];          // transposed + tf32-rounded
__device__ __align__(16) float g_out[XR*HH];
__device__ __align__(16) float g_ng4[(size_t)NCH*XR*HH];
__device__ __align__(16) float g_rs4[NCH*XR];
__device__ __align__(16) float g_sq [MINC];
__device__ __align__(16) float g_scal[4];     // 0: edge count, 1: neg_w, 2: loss
__device__ __align__(16) float g_weff[2*256];
__device__ int g_deg[NV];
__device__ int g_lst[NV*CAP];

__device__ __forceinline__ float tf32r(float x) {
    unsigned u;
    asm("cvt.rna.tf32.f32 %0, %1;" : "=r"(u) : "f"(x));
    return __uint_as_float(u);
}

__device__ __forceinline__ void mma8(float* d, unsigned a0, unsigned a1, unsigned a2,
                                     unsigned a3, unsigned b0, unsigned b1) {
    asm volatile("mma.sync.aligned.m16n8k8.row.col.f32.tf32.tf32.f32 "
                 "{%0,%1,%2,%3}, {%4,%5,%6,%7}, {%8,%9}, {%0,%1,%2,%3};"
                 : "+f"(d[0]), "+f"(d[1]), "+f"(d[2]), "+f"(d[3])
                 : "r"(a0), "r"(a1), "r"(a2), "r"(a3), "r"(b0), "r"(b1));
}

// ---------------- init ------------------------------------------------------
__global__ void k_init() {
    int i = blockIdx.x*blockDim.x + threadIdx.x;
    if (i < NV) g_deg[i] = 0;
    if (i == 0) { g_scal[0] = 0.f; g_scal[2] = 0.f; }
}

// ---------------- CSR-ish build: per-dst source lists -----------------------
__global__ void k_build(const int* __restrict__ src, const int* __restrict__ dst, int E) {
    int e = blockIdx.x*blockDim.x + threadIdx.x;
    if (e >= E) return;
    int d = dst[e];
    int slot = atomicAdd(&g_deg[d], 1);
    if (slot < CAP) g_lst[d*CAP + slot] = src[e];
}

// ---------------- gather segment-max: block per node, thread per feature ----
__global__ void k_gmax(const float* __restrict__ p, float* __restrict__ hn, int F) {
    __shared__ int sl[CAP];
    int node = blockIdx.x, t = threadIdx.x;
    int deg = min(g_deg[node], CAP);
    for (int e = t; e < deg; e += F) sl[e] = g_lst[node*CAP + e];
    __syncthreads();
    float m = -3.4e38f;
    for (int e = 0; e < deg; e++) m = fmaxf(m, p[(size_t)sl[e]*F + t]);
    hn[(size_t)node*F + t] = (deg > 0) ? m : 0.f;
}

// ---------------- 3xTF32 tensor-core GEMM (fp32-accurate) -------------------
// C[.,col] = act( A1@B1^T (+ A2@B2^T) + bias ).  A:[M,K] B:[N,K] row-major.
// Split each operand x = hi + lo (tf32 pieces); compute hi*hi + hi*lo + lo*hi.
// Tile 64x64, 256 threads (8 warps: wi=warp>>1 over 16 rows, wj=warp&1 over 32 cols).
__global__ void __launch_bounds__(256) k_tgemm(
    const float* __restrict__ A1, const float* __restrict__ B1, int K1,
    const float* __restrict__ A2, const float* __restrict__ B2, int K2,
    const float* __restrict__ bias, float* __restrict__ C,
    int N, int relu_f, int tf32_f)
{
    extern __shared__ float tsm[];
    float* sa_h = tsm;                 // [64][68]
    float* sa_l = tsm + 64*68;
    float* sb_h = tsm + 2*64*68;
    float* sb_l = tsm + 3*64*68;
    int t = threadIdx.x, lane = t & 31, warp = t >> 5;
    int wi = warp >> 1, wj = warp & 1;
    int g = lane >> 2, c = lane & 3;
    int m0 = blockIdx.y*64, n0 = blockIdx.x*64;

    float dg[4][4];
    #pragma unroll
    for (int nt = 0; nt < 4; nt++)
        #pragma unroll
        for (int q = 0; q < 4; q++) dg[nt][q] = 0.f;

    int nch = (K1 + K2) >> 6;
    for (int ch = 0; ch < nch; ch++) {
        int k0 = ch*64;
        const float* Ap; const float* Bp; int Kd;
        if (k0 < K1) { Ap = A1 + k0;        Bp = B1 + k0;        Kd = K1; }
        else         { Ap = A2 + (k0 - K1); Bp = B2 + (k0 - K1); Kd = K2; }
        __syncthreads();
        for (int l = t; l < 1024; l += 256) {
            int r = l >> 4, q = (l & 15) << 2;
            float4 v = *(const float4*)&Ap[(size_t)(m0 + r)*Kd + q];
            float4 vh, vl;
            vh.x = tf32r(v.x); vl.x = tf32r(v.x - vh.x);
            vh.y = tf32r(v.y); vl.y = tf32r(v.y - vh.y);
            vh.z = tf32r(v.z); vl.z = tf32r(v.z - vh.z);
            vh.w = tf32r(v.w); vl.w = tf32r(v.w - vh.w);
            *(float4*)&sa_h[r*68 + q] = vh;
            *(float4*)&sa_l[r*68 + q] = vl;
            float4 w = *(const float4*)&Bp[(size_t)(n0 + r)*Kd + q];
            float4 wh, wl;
            wh.x = tf32r(w.x); wl.x = tf32r(w.x - wh.x);
            wh.y = tf32r(w.y); wl.y = tf32r(w.y - wh.y);
            wh.z = tf32r(w.z); wl.z = tf32r(w.z - wh.z);
            wh.w = tf32r(w.w); wl.w = tf32r(w.w - wh.w);
            *(float4*)&sb_h[r*68 + q] = wh;
            *(float4*)&sb_l[r*68 + q] = wl;
        }
        __syncthreads();
        const float* Ah = sa_h + (wi*16)*68;
        const float* Al = sa_l + (wi*16)*68;
        const float* Bh = sb_h + (wj*32)*68;
        const float* Bl = sb_l + (wj*32)*68;
        #pragma unroll
        for (int ks = 0; ks < 8; ks++) {
            int k = ks*8;
            unsigned ah0 = __float_as_uint(Ah[(g    )*68 + k + c    ]);
            unsigned ah1 = __float_as_uint(Ah[(g + 8)*68 + k + c    ]);
            unsigned ah2 = __float_as_uint(Ah[(g    )*68 + k + c + 4]);
            unsigned ah3 = __float_as_uint(Ah[(g + 8)*68 + k + c + 4]);
            unsigned al0 = __float_as_uint(Al[(g    )*68 + k + c    ]);
            unsigned al1 = __float_as_uint(Al[(g + 8)*68 + k + c    ]);
            unsigned al2 = __float_as_uint(Al[(g    )*68 + k + c + 4]);
            unsigned al3 = __float_as_uint(Al[(g + 8)*68 + k + c + 4]);
            #pragma unroll
            for (int nt = 0; nt < 4; nt++) {
                unsigned bh0 = __float_as_uint(Bh[(nt*8 + g)*68 + k + c    ]);
                unsigned bh1 = __float_as_uint(Bh[(nt*8 + g)*68 + k + c + 4]);
                unsigned bl0 = __float_as_uint(Bl[(nt*8 + g)*68 + k + c    ]);
                unsigned bl1 = __float_as_uint(Bl[(nt*8 + g)*68 + k + c + 4]);
                mma8(dg[nt], ah0, ah1, ah2, ah3, bl0, bl1);
                mma8(dg[nt], al0, al1, al2, al3, bh0, bh1);
                mma8(dg[nt], ah0, ah1, ah2, ah3, bh0, bh1);
            }
        }
    }

    #pragma unroll
    for (int nt = 0; nt < 4; nt++) {
        int col = n0 + wj*32 + nt*8 + c*2;
        int r0  = m0 + wi*16 + g, r1 = r0 + 8;
        float bb0 = bias ? bias[col]     : 0.f;
        float bb1 = bias ? bias[col + 1] : 0.f;
        float v00 = dg[nt][0] + bb0, v01 = dg[nt][1] + bb1;
        float v10 = dg[nt][2] + bb0, v11 = dg[nt][3] + bb1;
        if (relu_f) {
            v00 = fmaxf(v00, 0.f); v01 = fmaxf(v01, 0.f);
            v10 = fmaxf(v10, 0.f); v11 = fmaxf(v11, 0.f);
        }
        if (tf32_f) {
            v00 = tf32r(v00); v01 = tf32r(v01);
            v10 = tf32r(v10); v11 = tf32r(v11);
        }
        *(float2*)&C[(size_t)r0*N + col] = make_float2(v00, v01);
        *(float2*)&C[(size_t)r1*N + col] = make_float2(v10, v11);
    }
}

// ---------------- relu + row l2norm -----------------------------------------
__global__ void k_relu_l2norm(float* __restrict__ h) {
    int r = blockIdx.x, t = threadIdx.x;
    float v = fmaxf(h[r*HH + t], 0.f);
    float s = v*v;
    #pragma unroll
    for (int o = 16; o; o >>= 1) s += __shfl_down_sync(0xffffffffu, s, o);
    __shared__ float ws[4];
    if ((t & 31) == 0) ws[t >> 5] = s;
    __syncthreads();
    float tot = ws[0] + ws[1] + ws[2] + ws[3];
    float nrm = fmaxf(sqrtf(tot), 1e-12f);
    h[r*HH + t] = v / nrm;
}

// ---------------- per-row squared norms -------------------------------------
__global__ void k_sq() {
    int r = blockIdx.x, t = threadIdx.x;
    float v = g_x[r*HH + t];
    float s = v*v;
    #pragma unroll
    for (int o = 16; o; o >>= 1) s += __shfl_down_sync(0xffffffffu, s, o);
    __shared__ float ws[4];
    if ((t & 31) == 0) ws[t >> 5] = s;
    __syncthreads();
    if (t == 0) g_sq[r] = ws[0] + ws[1] + ws[2] + ws[3];
}

// ---------------- SMOTE tiled -----------------------------------------------
__global__ void __launch_bounds__(256) k_smote2(const float* __restrict__ gaps) {
    __shared__ float4 ci[32*33];
    __shared__ float4 cj[32*33];
    __shared__ float  sqj[32];
    __shared__ int    snn[32];
    int t = threadIdx.x;
    int i0 = blockIdx.x*32;
    int ri = t >> 3, s = t & 7;

    const float4* srci = (const float4*)&g_x[(size_t)i0*HH];
    for (int l = t; l < 32*32; l += 256) {
        int r = l >> 5, kq = l & 31;
        ci[r*33 + kq] = srci[l];
    }
    __syncthreads();

    float sqi = g_sq[i0 + ri];
    int   gi  = i0 + ri;
    float best = 3.4e38f; int bestj = 0x7fffffff;

    for (int j0 = 0; j0 < MINC; j0 += 32) {
        __syncthreads();
        const float4* srcj = (const float4*)&g_x[(size_t)j0*HH];
        for (int l = t; l < 32*32; l += 256) {
            int r = l >> 5, kq = l & 31;
            cj[r*33 + kq] = srcj[l];
        }
        if (t < 32) sqj[t] = g_sq[j0 + t];
        __syncthreads();

        float d0=0.f,d1=0.f,d2=0.f,d3=0.f;
        #pragma unroll
        for (int kq = 0; kq < 32; kq++) {
            float4 a  = ci[ri*33 + kq];
            float4 b0 = cj[(s     )*33 + kq];
            float4 b1 = cj[(s +  8)*33 + kq];
            float4 b2 = cj[(s + 16)*33 + kq];
            float4 b3 = cj[(s + 24)*33 + kq];
            d0 += a.x*b0.x + a.y*b0.y + a.z*b0.z + a.w*b0.w;
            d1 += a.x*b1.x + a.y*b1.y + a.z*b1.z + a.w*b1.w;
            d2 += a.x*b2.x + a.y*b2.y + a.z*b2.z + a.w*b2.w;
            d3 += a.x*b3.x + a.y*b3.y + a.z*b3.z + a.w*b3.w;
        }
        float dd[4] = {d0,d1,d2,d3};
        #pragma unroll
        for (int m = 0; m < 4; m++) {
            int j = j0 + s + 8*m;
            float dv = sqi + sqj[s + 8*m] - 2.f*dd[m];
            if (j != gi) {
                if (dv < best || (dv == best && j < bestj)) { best = dv; bestj = j; }
            }
        }
    }
    #pragma unroll
    for (int o = 4; o; o >>= 1) {
        float ob = __shfl_down_sync(0xffffffffu, best, o);
        int   oj = __shfl_down_sync(0xffffffffu, bestj, o);
        if (ob < best || (ob == best && oj < bestj)) { best = ob; bestj = oj; }
    }
    if (s == 0) snn[ri] = bestj;
    __syncthreads();

    int r  = t >> 3;
    int c0 = (t & 7) * 16;
    int nn = snn[r];
    int gr = i0 + r;
    float ga = gaps[gr*REPC + 0], gb = gaps[gr*REPC + 1];
    #pragma unroll
    for (int u = 0; u < 16; u += 4) {
        float4 cv = ci[r*33 + ((c0 + u) >> 2)];
        float4 nv = *(const float4*)&g_x[(size_t)nn*HH + c0 + u];
        float4 oa, ob;
        oa.x = cv.x + ga*(nv.x - cv.x); oa.y = cv.y + ga*(nv.y - cv.y);
        oa.z = cv.z + ga*(nv.z - cv.z); oa.w = cv.w + ga*(nv.w - cv.w);
        ob.x = cv.x + gb*(nv.x - cv.x); ob.y = cv.y + gb*(nv.y - cv.y);
        ob.z = cv.z + gb*(nv.z - cv.z); ob.w = cv.w + gb*(nv.w - cv.w);
        *(float4*)&g_x[(size_t)(NV + 2*gr    )*HH + c0 + u] = oa;
        *(float4*)&g_x[(size_t)(NV + 2*gr + 1)*HH + c0 + u] = ob;
    }
}

// ---------------- count nonzero adj entries ---------------------------------
__global__ void k_count(const float* __restrict__ adj) {
    int i = blockIdx.x*blockDim.x + threadIdx.x;
    int T = gridDim.x*blockDim.x;
    float c = 0.f;
    for (long t = i; t < (long)NV*NV; t += T) c += (adj[t] != 0.f) ? 1.f : 0.f;
    #pragma unroll
    for (int o = 16; o; o >>= 1) c += __shfl_down_sync(0xffffffffu, c, o);
    __shared__ float ws[8];
    int tt = threadIdx.x;
    if ((tt & 31) == 0) ws[tt >> 5] = c;
    __syncthreads();
    if (tt == 0) {
        float s = 0.f;
        for (int q = 0; q < (int)(blockDim.x >> 5); q++) s += ws[q];
        atomicAdd(&g_scal[0], s);
    }
}
__global__ void k_negw() {
    float e = g_scal[0];
    g_scal[1] = e / (16777216.f - e);
}

// ---------------- build g_xt (transpose + tf32 round) -----------------------
__global__ void k_xt() {
    __shared__ float tl[32][33];
    int j0 = blockIdx.x*32, h0 = blockIdx.y*32;
    int tx = threadIdx.x, ty = threadIdx.y;  // (32,8)
    #pragma unroll
    for (int q = 0; q < 32; q += 8)
        tl[ty+q][tx] = g_x[(size_t)(j0+ty+q)*HH + h0 + tx];
    __syncthreads();
    #pragma unroll
    for (int q = 0; q < 32; q += 8)
        g_xt[(size_t)(h0+ty+q)*XR + j0 + tx] = tf32r(tl[tx][ty+q]);
}

// ---------------- fused tf32-MMA: gram -> sigmoid -> loss -> thresh -> neigh
__global__ void __launch_bounds__(256, 2) k_fused3(const float* __restrict__ adj) {
    extern __shared__ float dsm[];
    float* soi = dsm;                    // [64][132] out_i
    float* buf = dsm + 64*132;           // union: out_j [64][132] / xT [128][68]
    float* sp  = buf + 128*68;           // [64][68] thresholded P (tf32)
    float* srs = sp + 64*68;             // [2][64] rowsum partials
    float* lred = srs + 128;             // [8]

    int t    = threadIdx.x;
    int lane = t & 31, warp = t >> 5;
    int wi = warp >> 1, wj = warp & 1;
    int g  = lane >> 2, c = lane & 3;
    int i0 = blockIdx.x * 64;
    int chunk = blockIdx.y;
    int jbase = chunk * CHJ;
    bool lossi = (i0 < NV) && (chunk < 2);

    {
        const float4* src = (const float4*)&g_out[(size_t)i0*HH];
        float4* dstq = (float4*)soi;
        for (int l = t; l < 2048; l += 256) {
            int r = l >> 5, kq = l & 31;
            dstq[r*33 + kq] = src[l];
        }
    }

    float nacc[8][4];
    #pragma unroll
    for (int nt = 0; nt < 8; nt++)
        #pragma unroll
        for (int q = 0; q < 4; q++) nacc[nt][q] = 0.f;
    float rsum0 = 0.f, rsum1 = 0.f, lloss = 0.f;
    float negw = g_scal[1];

    const float* Ab = soi + (wi*16)*132;
    const float* Pb = sp  + (wi*16)*68;

    for (int jt = 0; jt < CHJ/64; jt++) {
        int j0 = jbase + jt*64;
        __syncthreads();
        {
            const float4* src = (const float4*)&g_out[(size_t)j0*HH];
            float4* dstq = (float4*)buf;
            for (int l = t; l < 2048; l += 256) {
                int r = l >> 5, kq = l & 31;
                dstq[r*33 + kq] = src[l];
            }
        }
        __syncthreads();

        float dg[4][4];
        #pragma unroll
        for (int nt = 0; nt < 4; nt++)
            #pragma unroll
            for (int q = 0; q < 4; q++) dg[nt][q] = 0.f;
        const float* Bb = buf + (wj*32)*132;
        #pragma unroll 4
        for (int ks = 0; ks < 16; ks++) {
            int k = ks*8;
            unsigned a0 = __float_as_uint(Ab[(g    )*132 + k + c    ]);
            unsigned a1 = __float_as_uint(Ab[(g + 8)*132 + k + c    ]);
            unsigned a2 = __float_as_uint(Ab[(g    )*132 + k + c + 4]);
            unsigned a3 = __float_as_uint(Ab[(g + 8)*132 + k + c + 4]);
            #pragma unroll
            for (int nt = 0; nt < 4; nt++) {
                unsigned b0 = __float_as_uint(Bb[(nt*8 + g)*132 + k + c    ]);
                unsigned b1 = __float_as_uint(Bb[(nt*8 + g)*132 + k + c + 4]);
                mma8(dg[nt], a0, a1, a2, a3, b0, b1);
            }
        }

        bool doloss = lossi;
        #pragma unroll
        for (int nt = 0; nt < 4; nt++) {
            int lj = wj*32 + nt*8 + c*2;
            int gj = j0 + lj;
            int r0 = i0 + wi*16 + g, r1 = r0 + 8;
            float p0 = 1.f/(1.f + __expf(-dg[nt][0]));
            float p1 = 1.f/(1.f + __expf(-dg[nt][1]));
            float p2 = 1.f/(1.f + __expf(-dg[nt][2]));
            float p3 = 1.f/(1.f + __expf(-dg[nt][3]));
            if (doloss) {
                float2 a0v = *(const float2*)&adj[(size_t)r0*NV + gj];
                float2 a1v = *(const float2*)&adj[(size_t)r1*NV + gj];
                float w0 = (a0v.x == 0.f) ? negw : 1.f;
                float w1 = (a0v.y == 0.f) ? negw : 1.f;
                float w2 = (a1v.x == 0.f) ? negw : 1.f;
                float w3 = (a1v.y == 0.f) ? negw : 1.f;
                float e0 = p0 - a0v.x, e1 = p1 - a0v.y;
                float e2 = p2 - a1v.x, e3 = p3 - a1v.y;
                lloss += w0*e0*e0 + w1*e1*e1 + w2*e2*e2 + w3*e3*e3;
            }
            float t0 = (p0 >= 0.5f) ? p0 : 0.f;
            float t1 = (p1 >= 0.5f) ? p1 : 0.f;
            float t2 = (p2 >= 0.5f) ? p2 : 0.f;
            float t3 = (p3 >= 0.5f) ? p3 : 0.f;
            rsum0 += t0 + t1;  rsum1 += t2 + t3;
            *(float2*)&sp[(wi*16 + g    )*68 + lj] = make_float2(tf32r(t0), tf32r(t1));
            *(float2*)&sp[(wi*16 + g + 8)*68 + lj] = make_float2(tf32r(t2), tf32r(t3));
        }
        __syncthreads();

        {
            const float* srcb = g_xt + j0;
            float4* dstq = (float4*)buf;
            for (int l = t; l < 2048; l += 256) {
                int h = l >> 4, q = l & 15;
                dstq[h*17 + q] = *(const float4*)&srcb[(size_t)h*XR + q*4];
            }
        }
        __syncthreads();

        #pragma unroll 2
        for (int ks = 0; ks < 8; ks++) {
            int k = ks*8;
            unsigned a0 = __float_as_uint(Pb[(g    )*68 + k + c    ]);
            unsigned a1 = __float_as_uint(Pb[(g + 8)*68 + k + c    ]);
            unsigned a2 = __float_as_uint(Pb[(g    )*68 + k + c + 4]);
            unsigned a3 = __float_as_uint(Pb[(g + 8)*68 + k + c + 4]);
            #pragma unroll
            for (int nt = 0; nt < 8; nt++) {
                unsigned b0 = __float_as_uint(buf[(wj*64 + nt*8 + g)*68 + k + c    ]);
                unsigned b1 = __float_as_uint(buf[(wj*64 + nt*8 + g)*68 + k + c + 4]);
                mma8(nacc[nt], a0, a1, a2, a3, b0, b1);
            }
        }
    }

    size_t cb = (size_t)chunk * XR;
    #pragma unroll
    for (int nt = 0; nt < 8; nt++) {
        int h = wj*64 + nt*8 + c*2;
        int r0 = i0 + wi*16 + g, r1 = r0 + 8;
        *(float2*)&g_ng4[(cb + r0)*HH + h] = make_float2(nacc[nt][0], nacc[nt][1]);
        *(float2*)&g_ng4[(cb + r1)*HH + h] = make_float2(nacc[nt][2], nacc[nt][3]);
    }

    #pragma unroll
    for (int o = 1; o <= 2; o <<= 1) {
        rsum0 += __shfl_xor_sync(0xffffffffu, rsum0, o);
        rsum1 += __shfl_xor_sync(0xffffffffu, rsum1, o);
    }
    if (c == 0) {
        srs[wj*64 + wi*16 + g    ] = rsum0;
        srs[wj*64 + wi*16 + g + 8] = rsum1;
    }
    #pragma unroll
    for (int o = 16; o; o >>= 1) lloss += __shfl_down_sync(0xffffffffu, lloss, o);
    if (lane == 0) lred[warp] = lloss;
    __syncthreads();
    if (t < 64) g_rs4[cb + i0 + t] = srs[t] + srs[64 + t];
    if (t == 0) {
        float s = 0.f;
        for (int q = 0; q < 8; q++) s += lred[q];
        atomicAdd(&g_scal[2], s);
    }
}

// ---------------- W_eff = W_clf @ W_conv  [2,256] ---------------------------
__global__ void k_weff(const float* __restrict__ Wclf, const float* __restrict__ Wconv) {
    int t = blockIdx.x*blockDim.x + threadIdx.x;
    if (t >= 512) return;
    int c = t >> 8, k = t & 255;
    float s = 0.f;
    for (int o = 0; o < HH; o++) s += Wclf[c*HH + o] * Wconv[o*256 + k];
    g_weff[c*256 + k] = s;
}

// ---------------- logits ----------------------------------------------------
__global__ void k_final(const float* __restrict__ bclf, float* __restrict__ ob) {
    int w = (blockIdx.x*blockDim.x + threadIdx.x) >> 5;
    int lane = threadIdx.x & 31;
    if (w >= XR) return;
    float rs = g_rs4[w] + g_rs4[XR + w] + g_rs4[2*XR + w];
    float inv = 1.f / (rs + 1.f);
    float l0 = 0.f, l1 = 0.f;
    for (int k = lane; k < HH; k += 32) {
        float xv = g_x[(size_t)w*HH + k];
        float nv = (g_ng4[(size_t)w*HH + k] + g_ng4[((size_t)XR + w)*HH + k]
                  + g_ng4[((size_t)2*XR + w)*HH + k]) * inv;
        l0 += xv*g_weff[k]       + nv*g_weff[128 + k];
        l1 += xv*g_weff[256 + k] + nv*g_weff[256 + 128 + k];
    }
    #pragma unroll
    for (int o = 16; o; o >>= 1) {
        l0 += __shfl_down_sync(0xffffffffu, l0, o);
        l1 += __shfl_down_sync(0xffffffffu, l1, o);
    }
    if (lane == 0) {
        ob[w*2 + 0] = l0 + bclf[0];
        ob[w*2 + 1] = l1 + bclf[1];
    }
}

// ---------------- y + loss tail ---------------------------------------------
__global__ void k_tail(const int* __restrict__ labels, float* __restrict__ ob) {
    int t = blockIdx.x*blockDim.x + threadIdx.x;
    if (t < XR)  ob[XR*2 + t] = (t < NV) ? (float)labels[t] : 1.f;
    if (t == XR) ob[XR*2 + XR] = g_scal[2];
}

// ---------------- launcher --------------------------------------------------
extern "C" void kernel_launch(void* const* d_in, const int* in_sizes, int n_in,
                              void* d_out, int out_size) {
    const float* feat     = (const float*)d_in[0];
    const float* adj      = (const float*)d_in[1];
    const int*   src      = (const int*)  d_in[2];
    const int*   dst      = (const int*)  d_in[3];
    const int*   labels   = (const int*)  d_in[4];
    const float* W_pool0  = (const float*)d_in[5];
    const float* b_pool0  = (const float*)d_in[6];
    const float* W_self0  = (const float*)d_in[7];
    const float* W_neigh0 = (const float*)d_in[8];
    const float* b0       = (const float*)d_in[9];
    const float* W_pool1  = (const float*)d_in[10];
    const float* b_pool1  = (const float*)d_in[11];
    const float* W_self1  = (const float*)d_in[12];
    const float* W_neigh1 = (const float*)d_in[13];
    const float* b1       = (const float*)d_in[14];
    const float* de_w     = (const float*)d_in[15];
    const float* W_conv   = (const float*)d_in[16];
    const float* W_clf    = (const float*)d_in[17];
    const float* b_clf    = (const float*)d_in[18];
    const float* gaps     = (const float*)d_in[19];
    int E = in_sizes[2];
    float* ob = (float*)d_out;

    float *p0, *hn0, *hh, *p1, *hn1, *xv, *ov;
    cudaGetSymbolAddress((void**)&p0,  g_p0);
    cudaGetSymbolAddress((void**)&hn0, g_hn0);
    cudaGetSymbolAddress((void**)&hh,  g_h);
    cudaGetSymbolAddress((void**)&p1,  g_p1);
    cudaGetSymbolAddress((void**)&hn1, g_hn1);
    cudaGetSymbolAddress((void**)&xv,  g_x);
    cudaGetSymbolAddress((void**)&ov,  g_out);

    const int FUSED_SMEM = (64*132 + 128*68 + 64*68 + 128 + 8) * 4;  // 86560 B
    const int TGEMM_SMEM = 4*64*68*4;                                // 69632 B
    cudaFuncSetAttribute(k_fused3, cudaFuncAttributeMaxDynamicSharedMemorySize, FUSED_SMEM);
    cudaFuncSetAttribute(k_tgemm,  cudaFuncAttributeMaxDynamicSharedMemorySize, TGEMM_SMEM);

    k_init<<<(NV+255)/256, 256>>>();
    k_build<<<(E+255)/256, 256>>>(src, dst, E);

    // layer 0
    k_tgemm<<<dim3(FIN/64, NV/64), 256, TGEMM_SMEM>>>(feat, W_pool0, FIN,
        (const float*)0, (const float*)0, 0, b_pool0, p0, FIN, 1, 0);
    k_gmax<<<NV, FIN>>>(p0, hn0, FIN);
    k_tgemm<<<dim3(HH/64, NV/64), 256, TGEMM_SMEM>>>(feat, W_self0, FIN, hn0, W_neigh0, FIN,
        b0, hh, HH, 0, 0);
    k_relu_l2norm<<<NV, HH>>>(hh);

    // layer 1
    k_tgemm<<<dim3(HH/64, NV/64), 256, TGEMM_SMEM>>>(hh, W_pool1, HH,
        (const float*)0, (const float*)0, 0, b_pool1, p1, HH, 1, 0);
    k_gmax<<<NV, HH>>>(p1, hn1, HH);
    k_tgemm<<<dim3(HH/64, NV/64), 256, TGEMM_SMEM>>>(hh, W_self1, HH, hn1, W_neigh1, HH,
        b1, xv, HH, 0, 0);

    // SMOTE
    k_sq<<<MINC, HH>>>();
    k_smote2<<<MINC/32, 256>>>(gaps);

    // decoder input (3xTF32, tf32-rounded epilogue feeds fused pass directly)
    k_tgemm<<<dim3(HH/64, XR/64), 256, TGEMM_SMEM>>>(xv, de_w, HH,
        (const float*)0, (const float*)0, 0, (const float*)0, ov, HH, 0, 1);
    k_xt<<<dim3(XR/32, HH/32), dim3(32, 8)>>>();

    // edge count + neg weight
    k_count<<<2048, 256>>>(adj);
    k_negw<<<1, 1>>>();

    // big fused pass (tensor cores)
    k_fused3<<<dim3(XR/64, NCH), 256, FUSED_SMEM>>>(adj);

    // classifier
    k_weff<<<2, 256>>>(W_clf, W_conv);
    k_final<<<XR/4, 128>>>(b_clf, ob);
    k_tail<<<(XR + 256)/256 + 1, 256>>>(labels, ob);
}